// round 7
// baseline (speedup 1.0000x reference)
#include <cuda_runtime.h>
#include <cuda_fp16.h>
#include <math.h>
#include <stdint.h>

// ---------------- model constants ----------------
#define TT   2048
#define DD   2048
#define HH   16
#define HDIM 128
#define SS   1024
#define BB   2
#define FFN  8192
#define QKN  2304
#define NL   2
#define LN_EPS 1e-5f
#define ATT_SCALE 0.08838834764831845f
#define ACC2_SCALE 3.0517578125e-05f   // 2^-15

// ---------------- fp32 scratch ----------------
__device__ float g_h   [TT * DD];
__device__ float g_res [TT * DD];
__device__ float g_res2[TT * DD];
__device__ float g_qkv [TT * QKN];
__device__ float g_attn[TT * DD];

// ---------------- activation splits: fp16 hi + e4m3 hi/lo ----------------
__device__ __align__(16) __half  g_xh[TT*DD];
__device__ __align__(16) uint8_t g_x8[TT*DD],  g_x8l[TT*DD];
__device__ __align__(16) __half  g_ch[TT*DD];
__device__ __align__(16) uint8_t g_c8[TT*DD],  g_c8l[TT*DD];
__device__ __align__(16) __half  g_fh[TT*FFN];
__device__ __align__(16) uint8_t g_f8[TT*FFN], g_f8l[TT*FFN];

// transposed weights [N][K]: fp16 hi + e4m3 hi(x32)/lo(x32768)
__device__ __align__(16) __half  g_wq[NL*QKN*DD];
__device__ __align__(16) uint8_t g_wq8[NL*QKN*DD], g_wq8l[NL*QKN*DD];
__device__ __align__(16) __half  g_wp[NL*DD*DD];
__device__ __align__(16) uint8_t g_wp8[NL*DD*DD],  g_wp8l[NL*DD*DD];
__device__ __align__(16) __half  g_wf[NL*FFN*DD];
__device__ __align__(16) uint8_t g_wf8[NL*FFN*DD], g_wf8l[NL*FFN*DD];
__device__ __align__(16) __half  g_wm[NL*DD*FFN];
__device__ __align__(16) uint8_t g_wm8[NL*DD*FFN], g_wm8l[NL*DD*FFN];

// ---------------- PTX helpers (plain sm_80/sm_89 features) ----------------
__device__ __forceinline__ uint32_t s2u(const void* p) {
    uint32_t a;
    asm("{ .reg .u64 t; cvta.to.shared.u64 t, %1; cvt.u32.u64 %0, t; }" : "=r"(a) : "l"(p));
    return a;
}
__device__ __forceinline__ uint32_t sw128(uint32_t o) { return o ^ ((o >> 3) & 0x70); }
__device__ __forceinline__ void cp16(uint32_t d, const void* s) {
    asm volatile("cp.async.cg.shared.global [%0], [%1], 16;" :: "r"(d), "l"(s));
}
#define CP_COMMIT() asm volatile("cp.async.commit_group;" ::: "memory")
#define CP_WAIT1()  asm volatile("cp.async.wait_group 1;" ::: "memory")
#define CP_WAIT0()  asm volatile("cp.async.wait_group 0;" ::: "memory")

#define LDSM4(R0, R1, R2, R3, ADDR) \
    asm volatile("ldmatrix.sync.aligned.m8n8.x4.shared.b16 {%0,%1,%2,%3}, [%4];" \
        : "=r"(R0), "=r"(R1), "=r"(R2), "=r"(R3) : "r"(ADDR))

#define MMA_F16(D, A, B0, B1) \
    asm volatile("mma.sync.aligned.m16n8k16.row.col.f32.f16.f16.f32 " \
        "{%0,%1,%2,%3}, {%4,%5,%6,%7}, {%8,%9}, {%0,%1,%2,%3};" \
        : "+f"((D)[0]), "+f"((D)[1]), "+f"((D)[2]), "+f"((D)[3]) \
        : "r"((A)[0]), "r"((A)[1]), "r"((A)[2]), "r"((A)[3]), "r"(B0), "r"(B1))

#define MMA_E4(D, A, B0, B1) \
    asm volatile("mma.sync.aligned.m16n8k32.row.col.f32.e4m3.e4m3.f32 " \
        "{%0,%1,%2,%3}, {%4,%5,%6,%7}, {%8,%9}, {%0,%1,%2,%3};" \
        : "+f"((D)[0]), "+f"((D)[1]), "+f"((D)[2]), "+f"((D)[3]) \
        : "r"((A)[0]), "r"((A)[1]), "r"((A)[2]), "r"((A)[3]), "r"(B0), "r"(B1))

// f32 -> e4m3 (satfinite), single byte (b -> lower byte)
__device__ __forceinline__ uint8_t f2e4m3(float x) {
    uint16_t r;
    asm("cvt.rn.satfinite.e4m3x2.f32 %0, %1, %2;" : "=h"(r) : "f"(0.f), "f"(x));
    return (uint8_t)r;
}
// pack two e4m3: byte0 = a, byte1 = b
__device__ __forceinline__ uint16_t f2e4m3x2(float a, float b) {
    uint16_t r;
    asm("cvt.rn.satfinite.e4m3x2.f32 %0, %1, %2;" : "=h"(r) : "f"(b), "f"(a));
    return r;
}

// ---------------- embed ----------------
__global__ void embed_kernel(const int* __restrict__ ids, const int* __restrict__ pos,
                             const float* __restrict__ wte, const float* __restrict__ wpe,
                             float* __restrict__ out)
{
    int idx = blockIdx.x * blockDim.x + threadIdx.x;
    if (idx >= TT * DD) return;
    int t = idx >> 11, d = idx & (DD - 1);
    out[idx] = wte[(size_t)ids[t] * DD + d] + wpe[(size_t)pos[t] * DD + d];
}

// ---------------- fused residual-add + LayerNorm (+ fp16/fp8 split out) ----------------
__global__ __launch_bounds__(256)
void ln_kernel(const float* __restrict__ a, const float* __restrict__ r,
               const float* __restrict__ g, const float* __restrict__ b,
               float* __restrict__ res_out, float* __restrict__ xf,
               __half* __restrict__ xh, uint8_t* __restrict__ x8, uint8_t* __restrict__ x8l)
{
    const int t = blockIdx.x;
    const size_t base = (size_t)t * DD;
    float v[8];
    float s = 0.f, sq = 0.f;
#pragma unroll
    for (int i = 0; i < 8; i++) {
        int idx = threadIdx.x + i * 256;
        float val = a[base + idx];
        if (r) val += r[base + idx];
        v[i] = val; s += val; sq += val * val;
    }
    int lane = threadIdx.x & 31, wid = threadIdx.x >> 5;
#pragma unroll
    for (int o = 16; o; o >>= 1) {
        s  += __shfl_xor_sync(0xffffffffu, s,  o);
        sq += __shfl_xor_sync(0xffffffffu, sq, o);
    }
    __shared__ float shs[8], shq[8], smean, srstd;
    if (lane == 0) { shs[wid] = s; shq[wid] = sq; }
    __syncthreads();
    if (threadIdx.x == 0) {
        float ts = 0.f, tq = 0.f;
#pragma unroll
        for (int i = 0; i < 8; i++) { ts += shs[i]; tq += shq[i]; }
        float mean = ts * (1.f / DD);
        float var  = tq * (1.f / DD) - mean * mean;
        smean = mean; srstd = rsqrtf(var + LN_EPS);
    }
    __syncthreads();
    float mean = smean, rstd = srstd;
#pragma unroll
    for (int i = 0; i < 8; i++) {
        int idx = threadIdx.x + i * 256;
        if (res_out) res_out[base + idx] = v[i];
        float y = (v[i] - mean) * rstd * g[idx] + b[idx];
        if (xf) xf[base + idx] = y;
        if (xh) {
            __half hh = __float2half_rn(y);
            float hf = __half2float(hh);
            xh[base + idx]  = hh;
            x8[base + idx]  = f2e4m3(hf);
            x8l[base + idx] = f2e4m3((y - hf) * 1024.f);   // A-lo scale 2^10
        }
    }
}

// ---------------- weight transpose + split: W[K][N] -> fp16[N][K] + e4m3 hi/lo ----------------
__global__ __launch_bounds__(256)
void tsplit_kernel(const float* __restrict__ W, __half* __restrict__ Th,
                   uint8_t* __restrict__ T8, uint8_t* __restrict__ T8l, int K, int N)
{
    __shared__ float t[32][33];
    int k0 = blockIdx.y * 32, n0 = blockIdx.x * 32;
    int tx = threadIdx.x & 31, ty = threadIdx.x >> 5;
#pragma unroll
    for (int i = 0; i < 4; i++)
        t[ty + i * 8][tx] = W[(size_t)(k0 + ty + i * 8) * N + n0 + tx];
    __syncthreads();
#pragma unroll
    for (int i = 0; i < 4; i++) {
        int n = ty + i * 8;
        float v = t[tx][n];
        __half h = __float2half_rn(v);
        float hf = __half2float(h);
        size_t o = (size_t)(n0 + n) * K + k0 + tx;
        Th[o]  = h;
        T8[o]  = f2e4m3(hf * 32.f);                 // B-hi scale 2^5
        T8l[o] = f2e4m3((v - hf) * 32768.f);        // B-lo scale 2^15
    }
}

// ---------------- fp16+fp8 warp-MMA GEMM ----------------
// C = A @ B^T + bias. CTA 128x128, K-chunk 64, 8 warps (2x4), warp tile 64x32.
// Buffer (64KB): A fp16 16KB | A fp8 hi/lo interleaved 16KB | B fp16 16KB | B fp8 16KB.
// Double buffered = 128KB.
#define SMEM_GEMM 131072
#define BUFSZ 65536

__device__ __forceinline__ void load_tiles(
    const __half* Ah, const uint8_t* A8, const uint8_t* A8l,
    const __half* Bh, const uint8_t* B8, const uint8_t* B8l,
    uint32_t base, int bm, int bn, int k0, int K, int tid)
{
#pragma unroll
    for (int i = 0; i < 4; i++) {                 // A fp16: 128 rows x 8 segs
        int idx = tid + i * 256;
        int row = idx >> 3, seg = idx & 7;
        cp16(base + sw128(row * 128 + seg * 16),
             Ah + (size_t)(bm + row) * K + k0 + seg * 8);
    }
#pragma unroll
    for (int i = 0; i < 4; i++) {                 // A fp8: sel(1)|row(7)|seg(2)
        int idx = tid + i * 256;
        int sel = idx >> 9, row = (idx >> 2) & 127, seg = idx & 3;
        const uint8_t* src = (sel ? A8l : A8) + (size_t)(bm + row) * K + k0 + seg * 16;
        cp16(base + 16384 + sw128(row * 128 + sel * 64 + seg * 16), src);
    }
#pragma unroll
    for (int i = 0; i < 4; i++) {                 // B fp16
        int idx = tid + i * 256;
        int row = idx >> 3, seg = idx & 7;
        cp16(base + 32768 + sw128(row * 128 + seg * 16),
             Bh + (size_t)(bn + row) * K + k0 + seg * 8);
    }
#pragma unroll
    for (int i = 0; i < 4; i++) {                 // B fp8
        int idx = tid + i * 256;
        int sel = idx >> 9, row = (idx >> 2) & 127, seg = idx & 3;
        const uint8_t* src = (sel ? B8l : B8) + (size_t)(bn + row) * K + k0 + seg * 16;
        cp16(base + 49152 + sw128(row * 128 + sel * 64 + seg * 16), src);
    }
}

__device__ __forceinline__ float gelu_tanh(float x) {
    float x3 = x * x * x;
    float t = tanhf(0.7978845608028654f * (x + 0.044715f * x3));
    return 0.5f * x * (1.f + t);
}

__global__ __launch_bounds__(256)
void gemm_kernel(const __half* __restrict__ Ah, const uint8_t* __restrict__ A8,
                 const uint8_t* __restrict__ A8l,
                 const __half* __restrict__ Bh, const uint8_t* __restrict__ B8,
                 const uint8_t* __restrict__ B8l,
                 const float* __restrict__ bias, float* __restrict__ Cf,
                 __half* __restrict__ Ch, uint8_t* __restrict__ C8,
                 uint8_t* __restrict__ C8l,
                 int M, int N, int K, int act)
{
    extern __shared__ char smem[];
    const uint32_t sb = s2u(smem);
    const int tid = threadIdx.x;
    const int bm = blockIdx.y * 128, bn = blockIdx.x * 128;
    const int lane = tid & 31, wid = tid >> 5;
    const int wm = wid >> 2, wn = wid & 3;

    const int lrow = lane & 15;
    const uint32_t lcol = (uint32_t)(lane >> 4) * 16;
    uint32_t aOff[4], bOff[2];
#pragma unroll
    for (int mf = 0; mf < 4; mf++)
        aOff[mf] = (uint32_t)(wm * 64 + mf * 16 + lrow) * 128 + lcol;
#pragma unroll
    for (int np = 0; np < 2; np++)
        bOff[np] = (uint32_t)(wn * 32 + np * 16 + lrow) * 128 + lcol;

    float acc[4][4][4], acc2[4][4][4];
#pragma unroll
    for (int i = 0; i < 4; i++)
#pragma unroll
        for (int j = 0; j < 4; j++)
#pragma unroll
            for (int c = 0; c < 4; c++) { acc[i][j][c] = 0.f; acc2[i][j][c] = 0.f; }

    const int nk = K >> 6;
    load_tiles(Ah, A8, A8l, Bh, B8, B8l, sb,         bm, bn, 0,  K, tid); CP_COMMIT();
    load_tiles(Ah, A8, A8l, Bh, B8, B8l, sb + BUFSZ, bm, bn, 64, K, tid); CP_COMMIT();

    for (int it = 0; it < nk; it++) {
        const int b = it & 1;
        if (it + 2 <= nk) { CP_WAIT1(); } else { CP_WAIT0(); }
        __syncthreads();

        const uint32_t ahS = sb + (uint32_t)b * BUFSZ;
        const uint32_t a8S = ahS + 16384;
        const uint32_t bhS = ahS + 32768;
        const uint32_t b8S = ahS + 49152;

        // ---- fp16 hi pass: 4 x k16 ----
#pragma unroll
        for (int ks = 0; ks < 4; ks++) {
            const uint32_t ko = (uint32_t)ks * 32;
            uint32_t ah[4][4], bh[2][4];
#pragma unroll
            for (int mf = 0; mf < 4; mf++)
                LDSM4(ah[mf][0], ah[mf][1], ah[mf][2], ah[mf][3], ahS + sw128(aOff[mf] + ko));
#pragma unroll
            for (int np = 0; np < 2; np++)
                LDSM4(bh[np][0], bh[np][1], bh[np][2], bh[np][3], bhS + sw128(bOff[np] + ko));
#pragma unroll
            for (int mf = 0; mf < 4; mf++)
#pragma unroll
                for (int nf = 0; nf < 4; nf++)
                    MMA_F16(acc[mf][nf], ah[mf], bh[nf >> 1][nf & 1], bh[nf >> 1][(nf & 1) + 2]);
        }

        // ---- fp8 correction passes: 2 x k32 ----
#pragma unroll
        for (int k8 = 0; k8 < 2; k8++) {
            const uint32_t ko = (uint32_t)k8 * 32;
            uint32_t a8h[4][4], a8l[4][4], b8h[2][4], b8l[2][4];
#pragma unroll
            for (int mf = 0; mf < 4; mf++) {
                LDSM4(a8h[mf][0], a8h[mf][1], a8h[mf][2], a8h[mf][3], a8S + sw128(aOff[mf] + ko));
                LDSM4(a8l[mf][0], a8l[mf][1], a8l[mf][2], a8l[mf][3], a8S + sw128(aOff[mf] + 64 + ko));
            }
#pragma unroll
            for (int np = 0; np < 2; np++) {
                LDSM4(b8h[np][0], b8h[np][1], b8h[np][2], b8h[np][3], b8S + sw128(bOff[np] + ko));
                LDSM4(b8l[np][0], b8l[np][1], b8l[np][2], b8l[np][3], b8S + sw128(bOff[np] + 64 + ko));
            }
            // pass 2: Ah8 * Bl8   (scale 2^0 * 2^15)
#pragma unroll
            for (int mf = 0; mf < 4; mf++)
#pragma unroll
                for (int nf = 0; nf < 4; nf++)
                    MMA_E4(acc2[mf][nf], a8h[mf], b8l[nf >> 1][nf & 1], b8l[nf >> 1][(nf & 1) + 2]);
            // pass 3: Al8 * Bh8   (scale 2^10 * 2^5)
#pragma unroll
            for (int mf = 0; mf < 4; mf++)
#pragma unroll
                for (int nf = 0; nf < 4; nf++)
                    MMA_E4(acc2[mf][nf], a8l[mf], b8h[nf >> 1][nf & 1], b8h[nf >> 1][(nf & 1) + 2]);
        }

        __syncthreads();
        if (it + 2 < nk) {
            load_tiles(Ah, A8, A8l, Bh, B8, B8l, sb + (uint32_t)b * BUFSZ,
                       bm, bn, (it + 2) * 64, K, tid);
            CP_COMMIT();
        }
    }

    // epilogue: combine hi + scaled corrections, bias (+gelu), store
    const int g = lane >> 2, tg = lane & 3;
#pragma unroll
    for (int mf = 0; mf < 4; mf++) {
#pragma unroll
        for (int nf = 0; nf < 4; nf++) {
            const int col = bn + wn * 32 + nf * 8 + tg * 2;
            const float bxv = bias[col], byv = bias[col + 1];
#pragma unroll
            for (int half = 0; half < 2; half++) {
                const int row = bm + wm * 64 + mf * 16 + g + half * 8;
                float vx = acc[mf][nf][half * 2 + 0] + acc2[mf][nf][half * 2 + 0] * ACC2_SCALE + bxv;
                float vy = acc[mf][nf][half * 2 + 1] + acc2[mf][nf][half * 2 + 1] * ACC2_SCALE + byv;
                if (act) { vx = gelu_tanh(vx); vy = gelu_tanh(vy); }
                const size_t o = (size_t)row * N + col;
                if (Cf) { float2 f2 = make_float2(vx, vy); *(float2*)(Cf + o) = f2; }
                if (Ch) {
                    __half h0 = __float2half_rn(vx), h1 = __float2half_rn(vy);
                    *(__half2*)(Ch + o) = __halves2half2(h0, h1);
                    float f0 = __half2float(h0), f1 = __half2float(h1);
                    *(uint16_t*)(C8 + o)  = f2e4m3x2(f0, f1);
                    *(uint16_t*)(C8l + o) = f2e4m3x2((vx - f0) * 1024.f, (vy - f1) * 1024.f);
                }
            }
        }
    }
}

// ---------------- MQA causal attention (writes ctx as fp16 + fp8 splits) ----------------
__global__ __launch_bounds__(256)
void attn_kernel(const float* __restrict__ qkv,
                 __half* __restrict__ ch, uint8_t* __restrict__ c8, uint8_t* __restrict__ c8l)
{
    const int gwarp = (blockIdx.x * blockDim.x + threadIdx.x) >> 5;
    const int lane  = threadIdx.x & 31;
    if (gwarp >= BB * HH * SS) return;

    const int s = gwarp & (SS - 1);
    const int h = (gwarp >> 10) & (HH - 1);
    const int b = gwarp >> 14;
    const int t = b * SS + s;

    const float4 q = *(const float4*)(qkv + (size_t)t * QKN + h * HDIM + lane * 4);
    const float* kb = qkv + (size_t)(b * SS) * QKN + DD;

    float m = -1e30f, l = 0.f;
    float4 acc = make_float4(0.f, 0.f, 0.f, 0.f);

    for (int j = 0; j <= s; j++) {
        const float* kp = kb + (size_t)j * QKN;
        float4 kv = *(const float4*)(kp + lane * 4);
        float p = q.x * kv.x + q.y * kv.y + q.z * kv.z + q.w * kv.w;
#pragma unroll
        for (int o = 16; o; o >>= 1) p += __shfl_xor_sync(0xffffffffu, p, o);
        p *= ATT_SCALE;
        float nm = fmaxf(m, p);
        float f = __expf(m - nm), e = __expf(p - nm);
        m = nm; l = l * f + e;
        float4 vv = *(const float4*)(kp + HDIM + lane * 4);
        acc.x = acc.x * f + e * vv.x;
        acc.y = acc.y * f + e * vv.y;
        acc.z = acc.z * f + e * vv.z;
        acc.w = acc.w * f + e * vv.w;
    }
    float inv = 1.f / l;
    float o4[4] = { acc.x * inv, acc.y * inv, acc.z * inv, acc.w * inv };
    size_t off = (size_t)t * DD + h * HDIM + lane * 4;
    __half h0 = __float2half_rn(o4[0]), h1 = __float2half_rn(o4[1]);
    __half h2 = __float2half_rn(o4[2]), h3 = __float2half_rn(o4[3]);
    *(__half2*)(ch + off)     = __halves2half2(h0, h1);
    *(__half2*)(ch + off + 2) = __halves2half2(h2, h3);
    float f0 = __half2float(h0), f1 = __half2float(h1);
    float f2v = __half2float(h2), f3 = __half2float(h3);
    uint32_t hi8 = (uint32_t)f2e4m3x2(f0, f1) | ((uint32_t)f2e4m3x2(f2v, f3) << 16);
    uint32_t lo8 = (uint32_t)f2e4m3x2((o4[0] - f0) * 1024.f, (o4[1] - f1) * 1024.f)
                 | ((uint32_t)f2e4m3x2((o4[2] - f2v) * 1024.f, (o4[3] - f3) * 1024.f) << 16);
    *(uint32_t*)(c8 + off)  = hi8;
    *(uint32_t*)(c8l + off) = lo8;
}

// ---------------- launch ----------------
extern "C" void kernel_launch(void* const* d_in, const int* in_sizes, int n_in,
                              void* d_out, int out_size)
{
    const int*   ids      = (const int*)  d_in[0];
    const int*   pos      = (const int*)  d_in[1];
    const float* wte      = (const float*)d_in[2];
    const float* wpe      = (const float*)d_in[3];
    const float* c_attn_w = (const float*)d_in[4];
    const float* c_attn_b = (const float*)d_in[5];
    const float* c_proj_w = (const float*)d_in[6];
    const float* c_proj_b = (const float*)d_in[7];
    const float* ln1_w    = (const float*)d_in[8];
    const float* ln1_b    = (const float*)d_in[9];
    const float* ln2_w    = (const float*)d_in[10];
    const float* ln2_b    = (const float*)d_in[11];
    const float* fc_w     = (const float*)d_in[12];
    const float* fc_b     = (const float*)d_in[13];
    const float* mp_w     = (const float*)d_in[14];
    const float* mp_b     = (const float*)d_in[15];
    const float* lnf_w    = (const float*)d_in[16];
    const float* lnf_b    = (const float*)d_in[17];
    float* out = (float*)d_out;

    float *h, *res, *res2, *qkv, *attn;
    __half *xh, *ch, *fh, *wq, *wp, *wf, *wm;
    uint8_t *x8, *x8l, *c8, *c8l, *f8, *f8l;
    uint8_t *wq8, *wq8l, *wp8, *wp8l, *wf8, *wf8l, *wm8, *wm8l;
    cudaGetSymbolAddress((void**)&h,    g_h);
    cudaGetSymbolAddress((void**)&res,  g_res);
    cudaGetSymbolAddress((void**)&res2, g_res2);
    cudaGetSymbolAddress((void**)&qkv,  g_qkv);
    cudaGetSymbolAddress((void**)&attn, g_attn);
    cudaGetSymbolAddress((void**)&xh,   g_xh);
    cudaGetSymbolAddress((void**)&x8,   g_x8);
    cudaGetSymbolAddress((void**)&x8l,  g_x8l);
    cudaGetSymbolAddress((void**)&ch,   g_ch);
    cudaGetSymbolAddress((void**)&c8,   g_c8);
    cudaGetSymbolAddress((void**)&c8l,  g_c8l);
    cudaGetSymbolAddress((void**)&fh,   g_fh);
    cudaGetSymbolAddress((void**)&f8,   g_f8);
    cudaGetSymbolAddress((void**)&f8l,  g_f8l);
    cudaGetSymbolAddress((void**)&wq,   g_wq);
    cudaGetSymbolAddress((void**)&wq8,  g_wq8);
    cudaGetSymbolAddress((void**)&wq8l, g_wq8l);
    cudaGetSymbolAddress((void**)&wp,   g_wp);
    cudaGetSymbolAddress((void**)&wp8,  g_wp8);
    cudaGetSymbolAddress((void**)&wp8l, g_wp8l);
    cudaGetSymbolAddress((void**)&wf,   g_wf);
    cudaGetSymbolAddress((void**)&wf8,  g_wf8);
    cudaGetSymbolAddress((void**)&wf8l, g_wf8l);
    cudaGetSymbolAddress((void**)&wm,   g_wm);
    cudaGetSymbolAddress((void**)&wm8,  g_wm8);
    cudaGetSymbolAddress((void**)&wm8l, g_wm8l);

    cudaFuncSetAttribute(gemm_kernel, cudaFuncAttributeMaxDynamicSharedMemorySize, SMEM_GEMM);

    // weight transposes + splits
    for (int l = 0; l < NL; l++) {
        tsplit_kernel<<<dim3(QKN / 32, DD / 32), 256>>>(
            c_attn_w + (size_t)l * DD * QKN,
            wq + (size_t)l * QKN * DD, wq8 + (size_t)l * QKN * DD, wq8l + (size_t)l * QKN * DD,
            DD, QKN);
        tsplit_kernel<<<dim3(DD / 32, DD / 32), 256>>>(
            c_proj_w + (size_t)l * DD * DD,
            wp + (size_t)l * DD * DD, wp8 + (size_t)l * DD * DD, wp8l + (size_t)l * DD * DD,
            DD, DD);
        tsplit_kernel<<<dim3(FFN / 32, DD / 32), 256>>>(
            fc_w + (size_t)l * DD * FFN,
            wf + (size_t)l * FFN * DD, wf8 + (size_t)l * FFN * DD, wf8l + (size_t)l * FFN * DD,
            DD, FFN);
        tsplit_kernel<<<dim3(DD / 32, FFN / 32), 256>>>(
            mp_w + (size_t)l * FFN * DD,
            wm + (size_t)l * DD * FFN, wm8 + (size_t)l * DD * FFN, wm8l + (size_t)l * DD * FFN,
            FFN, DD);
    }

    embed_kernel<<<(TT * DD + 255) / 256, 256>>>(ids, pos, wte, wpe, h);

    for (int l = 0; l < NL; l++) {
        ln_kernel<<<TT, 256>>>(h, (l == 0) ? nullptr : res2,
                               ln1_w + (size_t)l * DD, ln1_b + (size_t)l * DD,
                               res, nullptr, xh, x8, x8l);
        gemm_kernel<<<dim3(QKN / 128, TT / 128), 256, SMEM_GEMM>>>(
            xh, x8, x8l,
            wq + (size_t)l * QKN * DD, wq8 + (size_t)l * QKN * DD, wq8l + (size_t)l * QKN * DD,
            c_attn_b + (size_t)l * QKN, qkv, nullptr, nullptr, nullptr, TT, QKN, DD, 0);
        attn_kernel<<<(BB * HH * SS * 32 + 255) / 256, 256>>>(qkv, ch, c8, c8l);
        gemm_kernel<<<dim3(DD / 128, TT / 128), 256, SMEM_GEMM>>>(
            ch, c8, c8l,
            wp + (size_t)l * DD * DD, wp8 + (size_t)l * DD * DD, wp8l + (size_t)l * DD * DD,
            c_proj_b + (size_t)l * DD, attn, nullptr, nullptr, nullptr, TT, DD, DD, 0);
        ln_kernel<<<TT, 256>>>(attn, res,
                               ln2_w + (size_t)l * DD, ln2_b + (size_t)l * DD,
                               res2, nullptr, xh, x8, x8l);
        gemm_kernel<<<dim3(FFN / 128, TT / 128), 256, SMEM_GEMM>>>(
            xh, x8, x8l,
            wf + (size_t)l * FFN * DD, wf8 + (size_t)l * FFN * DD, wf8l + (size_t)l * FFN * DD,
            fc_b + (size_t)l * FFN, nullptr, fh, f8, f8l, TT, FFN, DD, 1);
        gemm_kernel<<<dim3(DD / 128, TT / 128), 256, SMEM_GEMM>>>(
            fh, f8, f8l,
            wm + (size_t)l * DD * FFN, wm8 + (size_t)l * DD * FFN, wm8l + (size_t)l * DD * FFN,
            mp_b + (size_t)l * DD, h, nullptr, nullptr, nullptr, TT, DD, FFN, 0);
    }

    ln_kernel<<<TT, 256>>>(h, res2, lnf_w, lnf_b, nullptr, out, nullptr, nullptr, nullptr);
}

// round 8
// speedup vs baseline: 1.4005x; 1.4005x over previous
#include <cuda_runtime.h>
#include <cuda_fp16.h>
#include <math.h>
#include <stdint.h>

// ---------------- model constants ----------------
#define TT   2048
#define DD   2048
#define HH   16
#define HDIM 128
#define SS   1024
#define BB   2
#define FFN  8192
#define QKN  2304
#define NL   2
#define LN_EPS 1e-5f
#define ATT_SCALE 0.08838834764831845f

// ---------------- fp32 scratch ----------------
__device__ float g_h   [TT * DD];
__device__ float g_res [TT * DD];
__device__ float g_res2[TT * DD];
__device__ float g_qkv [TT * QKN];
__device__ float g_attn[TT * DD];

// ---------------- fp16 two-limb activations ----------------
__device__ __align__(16) __half g_xh[TT*DD],  g_xl[TT*DD];
__device__ __align__(16) __half g_ch[TT*DD],  g_cl[TT*DD];
__device__ __align__(16) __half g_fh[TT*FFN], g_fl[TT*FFN];

// transposed weights [N][K], fp16 single-limb
__device__ __align__(16) __half g_wq[NL*QKN*DD];
__device__ __align__(16) __half g_wp[NL*DD*DD];
__device__ __align__(16) __half g_wf[NL*FFN*DD];
__device__ __align__(16) __half g_wm[NL*DD*FFN];

// ---------------- PTX helpers (plain sm_80 features) ----------------
__device__ __forceinline__ uint32_t s2u(const void* p) {
    uint32_t a;
    asm("{ .reg .u64 t; cvta.to.shared.u64 t, %1; cvt.u32.u64 %0, t; }" : "=r"(a) : "l"(p));
    return a;
}
__device__ __forceinline__ uint32_t sw128(uint32_t o) { return o ^ ((o >> 3) & 0x70); }
__device__ __forceinline__ void cp16(uint32_t d, const void* s) {
    asm volatile("cp.async.cg.shared.global [%0], [%1], 16;" :: "r"(d), "l"(s));
}
#define CP_COMMIT() asm volatile("cp.async.commit_group;" ::: "memory")
#define CP_WAIT1()  asm volatile("cp.async.wait_group 1;" ::: "memory")
#define CP_WAIT0()  asm volatile("cp.async.wait_group 0;" ::: "memory")

#define LDSM4(R0, R1, R2, R3, ADDR) \
    asm volatile("ldmatrix.sync.aligned.m8n8.x4.shared.b16 {%0,%1,%2,%3}, [%4];" \
        : "=r"(R0), "=r"(R1), "=r"(R2), "=r"(R3) : "r"(ADDR))

#define MMA_F16(D, A, B0, B1) \
    asm volatile("mma.sync.aligned.m16n8k16.row.col.f32.f16.f16.f32 " \
        "{%0,%1,%2,%3}, {%4,%5,%6,%7}, {%8,%9}, {%0,%1,%2,%3};" \
        : "+f"((D)[0]), "+f"((D)[1]), "+f"((D)[2]), "+f"((D)[3]) \
        : "r"((A)[0]), "r"((A)[1]), "r"((A)[2]), "r"((A)[3]), "r"(B0), "r"(B1))

// ---------------- embed ----------------
__global__ void embed_kernel(const int* __restrict__ ids, const int* __restrict__ pos,
                             const float* __restrict__ wte, const float* __restrict__ wpe,
                             float* __restrict__ out)
{
    int idx = blockIdx.x * blockDim.x + threadIdx.x;
    if (idx >= TT * DD) return;
    int t = idx >> 11, d = idx & (DD - 1);
    out[idx] = wte[(size_t)ids[t] * DD + d] + wpe[(size_t)pos[t] * DD + d];
}

// ---------------- fused residual-add + LayerNorm (+ fp16 hi/lo split out) ----------------
__global__ __launch_bounds__(256)
void ln_kernel(const float* __restrict__ a, const float* __restrict__ r,
               const float* __restrict__ g, const float* __restrict__ b,
               float* __restrict__ res_out, float* __restrict__ xf,
               __half* __restrict__ xh, __half* __restrict__ xl)
{
    const int t = blockIdx.x;
    const size_t base = (size_t)t * DD;
    float v[8];
    float s = 0.f, sq = 0.f;
#pragma unroll
    for (int i = 0; i < 8; i++) {
        int idx = threadIdx.x + i * 256;
        float val = a[base + idx];
        if (r) val += r[base + idx];
        v[i] = val; s += val; sq += val * val;
    }
    int lane = threadIdx.x & 31, wid = threadIdx.x >> 5;
#pragma unroll
    for (int o = 16; o; o >>= 1) {
        s  += __shfl_xor_sync(0xffffffffu, s,  o);
        sq += __shfl_xor_sync(0xffffffffu, sq, o);
    }
    __shared__ float shs[8], shq[8], smean, srstd;
    if (lane == 0) { shs[wid] = s; shq[wid] = sq; }
    __syncthreads();
    if (threadIdx.x == 0) {
        float ts = 0.f, tq = 0.f;
#pragma unroll
        for (int i = 0; i < 8; i++) { ts += shs[i]; tq += shq[i]; }
        float mean = ts * (1.f / DD);
        float var  = tq * (1.f / DD) - mean * mean;
        smean = mean; srstd = rsqrtf(var + LN_EPS);
    }
    __syncthreads();
    float mean = smean, rstd = srstd;
#pragma unroll
    for (int i = 0; i < 8; i++) {
        int idx = threadIdx.x + i * 256;
        if (res_out) res_out[base + idx] = v[i];
        float y = (v[i] - mean) * rstd * g[idx] + b[idx];
        if (xf) xf[base + idx] = y;
        if (xh) {
            __half hh = __float2half_rn(y);
            xh[base + idx] = hh;
            xl[base + idx] = __float2half_rn(y - __half2float(hh));
        }
    }
}

// ---------------- weight transpose: W[K][N] -> fp16[N][K] ----------------
__global__ __launch_bounds__(256)
void tsplit_kernel(const float* __restrict__ W, __half* __restrict__ Th, int K, int N)
{
    __shared__ float t[32][33];
    int k0 = blockIdx.y * 32, n0 = blockIdx.x * 32;
    int tx = threadIdx.x & 31, ty = threadIdx.x >> 5;
#pragma unroll
    for (int i = 0; i < 4; i++)
        t[ty + i * 8][tx] = W[(size_t)(k0 + ty + i * 8) * N + n0 + tx];
    __syncthreads();
#pragma unroll
    for (int i = 0; i < 4; i++) {
        int n = ty + i * 8;
        Th[(size_t)(n0 + n) * K + k0 + tx] = __float2half_rn(t[tx][n]);
    }
}

// ---------------- fp16 two-limb warp-MMA GEMM ----------------
// C = (Ah+Al) @ Bh^T + bias. CTA 128x128, K-chunk 64, 8 warps (2x4), warp 64x32.
// Buffer (48KB): Ah 16KB | Al 16KB | Bh 16KB. Double buffered = 96KB, 2 CTAs/SM.
#define SMEM_GEMM 98304
#define BUFSZ 49152

__device__ __forceinline__ void load_tiles(
    const __half* Ah, const __half* Al, const __half* Bh,
    uint32_t base, int bm, int bn, int k0, int K, int tid)
{
#pragma unroll
    for (int i = 0; i < 4; i++) {                 // A-hi: 128 rows x 8 segs
        int idx = tid + i * 256;
        int row = idx >> 3, seg = idx & 7;
        cp16(base + sw128(row * 128 + seg * 16),
             Ah + (size_t)(bm + row) * K + k0 + seg * 8);
    }
#pragma unroll
    for (int i = 0; i < 4; i++) {                 // A-lo
        int idx = tid + i * 256;
        int row = idx >> 3, seg = idx & 7;
        cp16(base + 16384 + sw128(row * 128 + seg * 16),
             Al + (size_t)(bm + row) * K + k0 + seg * 8);
    }
#pragma unroll
    for (int i = 0; i < 4; i++) {                 // B-hi
        int idx = tid + i * 256;
        int row = idx >> 3, seg = idx & 7;
        cp16(base + 32768 + sw128(row * 128 + seg * 16),
             Bh + (size_t)(bn + row) * K + k0 + seg * 8);
    }
}

__device__ __forceinline__ float gelu_tanh(float x) {
    float x3 = x * x * x;
    float t = tanhf(0.7978845608028654f * (x + 0.044715f * x3));
    return 0.5f * x * (1.f + t);
}

__global__ __launch_bounds__(256, 2)
void gemm_kernel(const __half* __restrict__ Ah, const __half* __restrict__ Al,
                 const __half* __restrict__ Bh,
                 const float* __restrict__ bias, float* __restrict__ Cf,
                 __half* __restrict__ Ch, __half* __restrict__ Cl,
                 int M, int N, int K, int act)
{
    extern __shared__ char smem[];
    const uint32_t sb = s2u(smem);
    const int tid = threadIdx.x;
    const int bm = blockIdx.y * 128, bn = blockIdx.x * 128;
    const int lane = tid & 31, wid = tid >> 5;
    const int wm = wid >> 2, wn = wid & 3;

    const int lrow = lane & 15;
    const uint32_t lcol = (uint32_t)(lane >> 4) * 16;
    uint32_t aOff[4], bOff[2];
#pragma unroll
    for (int mf = 0; mf < 4; mf++)
        aOff[mf] = (uint32_t)(wm * 64 + mf * 16 + lrow) * 128 + lcol;
#pragma unroll
    for (int np = 0; np < 2; np++)
        bOff[np] = (uint32_t)(wn * 32 + np * 16 + lrow) * 128 + lcol;

    float acc[4][4][4];
#pragma unroll
    for (int i = 0; i < 4; i++)
#pragma unroll
        for (int j = 0; j < 4; j++)
#pragma unroll
            for (int c = 0; c < 4; c++) acc[i][j][c] = 0.f;

    const int nk = K >> 6;
    load_tiles(Ah, Al, Bh, sb,         bm, bn, 0,  K, tid); CP_COMMIT();
    load_tiles(Ah, Al, Bh, sb + BUFSZ, bm, bn, 64, K, tid); CP_COMMIT();

    for (int it = 0; it < nk; it++) {
        const int b = it & 1;
        if (it + 2 <= nk) { CP_WAIT1(); } else { CP_WAIT0(); }
        __syncthreads();

        const uint32_t ahS = sb + (uint32_t)b * BUFSZ;
        const uint32_t alS = ahS + 16384;
        const uint32_t bhS = ahS + 32768;

#pragma unroll
        for (int ks = 0; ks < 4; ks++) {
            const uint32_t ko = (uint32_t)ks * 32;
            uint32_t af[4][4], bh[2][4];
#pragma unroll
            for (int np = 0; np < 2; np++)
                LDSM4(bh[np][0], bh[np][1], bh[np][2], bh[np][3], bhS + sw128(bOff[np] + ko));
            // pass 1: Ah * Bh
#pragma unroll
            for (int mf = 0; mf < 4; mf++)
                LDSM4(af[mf][0], af[mf][1], af[mf][2], af[mf][3], ahS + sw128(aOff[mf] + ko));
#pragma unroll
            for (int mf = 0; mf < 4; mf++)
#pragma unroll
                for (int nf = 0; nf < 4; nf++)
                    MMA_F16(acc[mf][nf], af[mf], bh[nf >> 1][nf & 1], bh[nf >> 1][(nf & 1) + 2]);
            // pass 2: Al * Bh (reuse af regs)
#pragma unroll
            for (int mf = 0; mf < 4; mf++)
                LDSM4(af[mf][0], af[mf][1], af[mf][2], af[mf][3], alS + sw128(aOff[mf] + ko));
#pragma unroll
            for (int mf = 0; mf < 4; mf++)
#pragma unroll
                for (int nf = 0; nf < 4; nf++)
                    MMA_F16(acc[mf][nf], af[mf], bh[nf >> 1][nf & 1], bh[nf >> 1][(nf & 1) + 2]);
        }

        __syncthreads();
        if (it + 2 < nk) {
            load_tiles(Ah, Al, Bh, sb + (uint32_t)b * BUFSZ, bm, bn, (it + 2) * 64, K, tid);
            CP_COMMIT();
        }
    }

    // epilogue
    const int g = lane >> 2, tg = lane & 3;
#pragma unroll
    for (int mf = 0; mf < 4; mf++) {
#pragma unroll
        for (int nf = 0; nf < 4; nf++) {
            const int col = bn + wn * 32 + nf * 8 + tg * 2;
            const float bxv = bias[col], byv = bias[col + 1];
#pragma unroll
            for (int half = 0; half < 2; half++) {
                const int row = bm + wm * 64 + mf * 16 + g + half * 8;
                float vx = acc[mf][nf][half * 2 + 0] + bxv;
                float vy = acc[mf][nf][half * 2 + 1] + byv;
                if (act) { vx = gelu_tanh(vx); vy = gelu_tanh(vy); }
                const size_t o = (size_t)row * N + col;
                if (Cf) { float2 f2 = make_float2(vx, vy); *(float2*)(Cf + o) = f2; }
                if (Ch) {
                    __half h0 = __float2half_rn(vx), h1 = __float2half_rn(vy);
                    *(__half2*)(Ch + o) = __halves2half2(h0, h1);
                    *(__half2*)(Cl + o) = __halves2half2(
                        __float2half_rn(vx - __half2float(h0)),
                        __float2half_rn(vy - __half2float(h1)));
                }
            }
        }
    }
}

// ---------------- MQA causal attention (writes ctx as fp16 hi/lo) ----------------
__global__ __launch_bounds__(256)
void attn_kernel(const float* __restrict__ qkv,
                 __half* __restrict__ ch, __half* __restrict__ cl)
{
    const int gwarp = (blockIdx.x * blockDim.x + threadIdx.x) >> 5;
    const int lane  = threadIdx.x & 31;
    if (gwarp >= BB * HH * SS) return;

    const int s = gwarp & (SS - 1);
    const int h = (gwarp >> 10) & (HH - 1);
    const int b = gwarp >> 14;
    const int t = b * SS + s;

    const float4 q = *(const float4*)(qkv + (size_t)t * QKN + h * HDIM + lane * 4);
    const float* kb = qkv + (size_t)(b * SS) * QKN + DD;

    float m = -1e30f, l = 0.f;
    float4 acc = make_float4(0.f, 0.f, 0.f, 0.f);

    for (int j = 0; j <= s; j++) {
        const float* kp = kb + (size_t)j * QKN;
        float4 kv = *(const float4*)(kp + lane * 4);
        float p = q.x * kv.x + q.y * kv.y + q.z * kv.z + q.w * kv.w;
#pragma unroll
        for (int o = 16; o; o >>= 1) p += __shfl_xor_sync(0xffffffffu, p, o);
        p *= ATT_SCALE;
        float nm = fmaxf(m, p);
        float f = __expf(m - nm), e = __expf(p - nm);
        m = nm; l = l * f + e;
        float4 vv = *(const float4*)(kp + HDIM + lane * 4);
        acc.x = acc.x * f + e * vv.x;
        acc.y = acc.y * f + e * vv.y;
        acc.z = acc.z * f + e * vv.z;
        acc.w = acc.w * f + e * vv.w;
    }
    float inv = 1.f / l;
    float o4[4] = { acc.x * inv, acc.y * inv, acc.z * inv, acc.w * inv };
    size_t off = (size_t)t * DD + h * HDIM + lane * 4;
    __half h0 = __float2half_rn(o4[0]), h1 = __float2half_rn(o4[1]);
    __half h2 = __float2half_rn(o4[2]), h3 = __float2half_rn(o4[3]);
    *(__half2*)(ch + off)     = __halves2half2(h0, h1);
    *(__half2*)(ch + off + 2) = __halves2half2(h2, h3);
    *(__half2*)(cl + off)     = __halves2half2(
        __float2half_rn(o4[0] - __half2float(h0)),
        __float2half_rn(o4[1] - __half2float(h1)));
    *(__half2*)(cl + off + 2) = __halves2half2(
        __float2half_rn(o4[2] - __half2float(h2)),
        __float2half_rn(o4[3] - __half2float(h3)));
}

// ---------------- launch ----------------
extern "C" void kernel_launch(void* const* d_in, const int* in_sizes, int n_in,
                              void* d_out, int out_size)
{
    const int*   ids      = (const int*)  d_in[0];
    const int*   pos      = (const int*)  d_in[1];
    const float* wte      = (const float*)d_in[2];
    const float* wpe      = (const float*)d_in[3];
    const float* c_attn_w = (const float*)d_in[4];
    const float* c_attn_b = (const float*)d_in[5];
    const float* c_proj_w = (const float*)d_in[6];
    const float* c_proj_b = (const float*)d_in[7];
    const float* ln1_w    = (const float*)d_in[8];
    const float* ln1_b    = (const float*)d_in[9];
    const float* ln2_w    = (const float*)d_in[10];
    const float* ln2_b    = (const float*)d_in[11];
    const float* fc_w     = (const float*)d_in[12];
    const float* fc_b     = (const float*)d_in[13];
    const float* mp_w     = (const float*)d_in[14];
    const float* mp_b     = (const float*)d_in[15];
    const float* lnf_w    = (const float*)d_in[16];
    const float* lnf_b    = (const float*)d_in[17];
    float* out = (float*)d_out;

    float *h, *res, *res2, *qkv, *attn;
    __half *xh, *xl, *ch, *cl, *fh, *fl, *wq, *wp, *wf, *wm;
    cudaGetSymbolAddress((void**)&h,    g_h);
    cudaGetSymbolAddress((void**)&res,  g_res);
    cudaGetSymbolAddress((void**)&res2, g_res2);
    cudaGetSymbolAddress((void**)&qkv,  g_qkv);
    cudaGetSymbolAddress((void**)&attn, g_attn);
    cudaGetSymbolAddress((void**)&xh,   g_xh);
    cudaGetSymbolAddress((void**)&xl,   g_xl);
    cudaGetSymbolAddress((void**)&ch,   g_ch);
    cudaGetSymbolAddress((void**)&cl,   g_cl);
    cudaGetSymbolAddress((void**)&fh,   g_fh);
    cudaGetSymbolAddress((void**)&fl,   g_fl);
    cudaGetSymbolAddress((void**)&wq,   g_wq);
    cudaGetSymbolAddress((void**)&wp,   g_wp);
    cudaGetSymbolAddress((void**)&wf,   g_wf);
    cudaGetSymbolAddress((void**)&wm,   g_wm);

    cudaFuncSetAttribute(gemm_kernel, cudaFuncAttributeMaxDynamicSharedMemorySize, SMEM_GEMM);

    // weight transposes (fp16 single-limb)
    for (int l = 0; l < NL; l++) {
        tsplit_kernel<<<dim3(QKN / 32, DD / 32), 256>>>(
            c_attn_w + (size_t)l * DD * QKN, wq + (size_t)l * QKN * DD, DD, QKN);
        tsplit_kernel<<<dim3(DD / 32, DD / 32), 256>>>(
            c_proj_w + (size_t)l * DD * DD, wp + (size_t)l * DD * DD, DD, DD);
        tsplit_kernel<<<dim3(FFN / 32, DD / 32), 256>>>(
            fc_w + (size_t)l * DD * FFN, wf + (size_t)l * FFN * DD, DD, FFN);
        tsplit_kernel<<<dim3(DD / 32, FFN / 32), 256>>>(
            mp_w + (size_t)l * FFN * DD, wm + (size_t)l * DD * FFN, FFN, DD);
    }

    embed_kernel<<<(TT * DD + 255) / 256, 256>>>(ids, pos, wte, wpe, h);

    for (int l = 0; l < NL; l++) {
        ln_kernel<<<TT, 256>>>(h, (l == 0) ? nullptr : res2,
                               ln1_w + (size_t)l * DD, ln1_b + (size_t)l * DD,
                               res, nullptr, xh, xl);
        gemm_kernel<<<dim3(QKN / 128, TT / 128), 256, SMEM_GEMM>>>(
            xh, xl, wq + (size_t)l * QKN * DD,
            c_attn_b + (size_t)l * QKN, qkv, nullptr, nullptr, TT, QKN, DD, 0);
        attn_kernel<<<(BB * HH * SS * 32 + 255) / 256, 256>>>(qkv, ch, cl);
        gemm_kernel<<<dim3(DD / 128, TT / 128), 256, SMEM_GEMM>>>(
            ch, cl, wp + (size_t)l * DD * DD,
            c_proj_b + (size_t)l * DD, attn, nullptr, nullptr, TT, DD, DD, 0);
        ln_kernel<<<TT, 256>>>(attn, res,
                               ln2_w + (size_t)l * DD, ln2_b + (size_t)l * DD,
                               res2, nullptr, xh, xl);
        gemm_kernel<<<dim3(FFN / 128, TT / 128), 256, SMEM_GEMM>>>(
            xh, xl, wf + (size_t)l * FFN * DD,
            fc_b + (size_t)l * FFN, nullptr, fh, fl, TT, FFN, DD, 1);
        gemm_kernel<<<dim3(DD / 128, TT / 128), 256, SMEM_GEMM>>>(
            fh, fl, wm + (size_t)l * DD * FFN,
            mp_b + (size_t)l * DD, h, nullptr, nullptr, TT, DD, FFN, 0);
    }

    ln_kernel<<<TT, 256>>>(h, res2, lnf_w, lnf_b, nullptr, out, nullptr, nullptr);
}

// round 9
// speedup vs baseline: 2.4852x; 1.7745x over previous
#include <cuda_runtime.h>
#include <cuda_fp16.h>
#include <math.h>
#include <stdint.h>

// ---------------- model constants ----------------
#define TT   2048
#define DD   2048
#define HH   16
#define HDIM 128
#define SS   1024
#define BB   2
#define FFN  8192
#define QKN  2304
#define NL   2
#define LN_EPS 1e-5f
#define ATT_SCALE 0.08838834764831845f

// ---------------- fp32 scratch ----------------
__device__ float g_h   [TT * DD];
__device__ float g_res [TT * DD];
__device__ float g_res2[TT * DD];
__device__ float g_qkv [TT * QKN];
__device__ float g_attn[TT * DD];

// ---------------- fp16 two-limb activations ----------------
__device__ __align__(16) __half g_xh[TT*DD],  g_xl[TT*DD];
__device__ __align__(16) __half g_ch[TT*DD],  g_cl[TT*DD];
__device__ __align__(16) __half g_fh[TT*FFN], g_fl[TT*FFN];

// transposed weights [N][K], fp16 single-limb
__device__ __align__(16) __half g_wq[NL*QKN*DD];
__device__ __align__(16) __half g_wp[NL*DD*DD];
__device__ __align__(16) __half g_wf[NL*FFN*DD];
__device__ __align__(16) __half g_wm[NL*DD*FFN];

// ---------------- PTX helpers (plain sm_80 features) ----------------
__device__ __forceinline__ uint32_t s2u(const void* p) {
    uint32_t a;
    asm("{ .reg .u64 t; cvta.to.shared.u64 t, %1; cvt.u32.u64 %0, t; }" : "=r"(a) : "l"(p));
    return a;
}
__device__ __forceinline__ uint32_t sw128(uint32_t o) { return o ^ ((o >> 3) & 0x70); }
__device__ __forceinline__ void cp16(uint32_t d, const void* s) {
    asm volatile("cp.async.cg.shared.global [%0], [%1], 16;" :: "r"(d), "l"(s));
}
#define CP_COMMIT() asm volatile("cp.async.commit_group;" ::: "memory")
#define CP_WAIT1()  asm volatile("cp.async.wait_group 1;" ::: "memory")
#define CP_WAIT0()  asm volatile("cp.async.wait_group 0;" ::: "memory")

#define LDSM4(R0, R1, R2, R3, ADDR) \
    asm volatile("ldmatrix.sync.aligned.m8n8.x4.shared.b16 {%0,%1,%2,%3}, [%4];" \
        : "=r"(R0), "=r"(R1), "=r"(R2), "=r"(R3) : "r"(ADDR))

#define MMA_F16(D, A, B0, B1) \
    asm volatile("mma.sync.aligned.m16n8k16.row.col.f32.f16.f16.f32 " \
        "{%0,%1,%2,%3}, {%4,%5,%6,%7}, {%8,%9}, {%0,%1,%2,%3};" \
        : "+f"((D)[0]), "+f"((D)[1]), "+f"((D)[2]), "+f"((D)[3]) \
        : "r"((A)[0]), "r"((A)[1]), "r"((A)[2]), "r"((A)[3]), "r"(B0), "r"(B1))

__device__ __forceinline__ uint32_t packh2(float a, float b) {
    __half2 t = __halves2half2(__float2half_rn(a), __float2half_rn(b));
    return *(uint32_t*)&t;
}

// ---------------- embed ----------------
__global__ void embed_kernel(const int* __restrict__ ids, const int* __restrict__ pos,
                             const float* __restrict__ wte, const float* __restrict__ wpe,
                             float* __restrict__ out)
{
    int idx = blockIdx.x * blockDim.x + threadIdx.x;
    if (idx >= TT * DD) return;
    int t = idx >> 11, d = idx & (DD - 1);
    out[idx] = wte[(size_t)ids[t] * DD + d] + wpe[(size_t)pos[t] * DD + d];
}

// ---------------- fused residual-add + LayerNorm (+ fp16 hi/lo split out) ----------------
__global__ __launch_bounds__(256)
void ln_kernel(const float* __restrict__ a, const float* __restrict__ r,
               const float* __restrict__ g, const float* __restrict__ b,
               float* __restrict__ res_out, float* __restrict__ xf,
               __half* __restrict__ xh, __half* __restrict__ xl)
{
    const int t = blockIdx.x;
    const size_t base = (size_t)t * DD;
    float v[8];
    float s = 0.f, sq = 0.f;
#pragma unroll
    for (int i = 0; i < 8; i++) {
        int idx = threadIdx.x + i * 256;
        float val = a[base + idx];
        if (r) val += r[base + idx];
        v[i] = val; s += val; sq += val * val;
    }
    int lane = threadIdx.x & 31, wid = threadIdx.x >> 5;
#pragma unroll
    for (int o = 16; o; o >>= 1) {
        s  += __shfl_xor_sync(0xffffffffu, s,  o);
        sq += __shfl_xor_sync(0xffffffffu, sq, o);
    }
    __shared__ float shs[8], shq[8], smean, srstd;
    if (lane == 0) { shs[wid] = s; shq[wid] = sq; }
    __syncthreads();
    if (threadIdx.x == 0) {
        float ts = 0.f, tq = 0.f;
#pragma unroll
        for (int i = 0; i < 8; i++) { ts += shs[i]; tq += shq[i]; }
        float mean = ts * (1.f / DD);
        float var  = tq * (1.f / DD) - mean * mean;
        smean = mean; srstd = rsqrtf(var + LN_EPS);
    }
    __syncthreads();
    float mean = smean, rstd = srstd;
#pragma unroll
    for (int i = 0; i < 8; i++) {
        int idx = threadIdx.x + i * 256;
        if (res_out) res_out[base + idx] = v[i];
        float y = (v[i] - mean) * rstd * g[idx] + b[idx];
        if (xf) xf[base + idx] = y;
        if (xh) {
            __half hh = __float2half_rn(y);
            xh[base + idx] = hh;
            xl[base + idx] = __float2half_rn(y - __half2float(hh));
        }
    }
}

// ---------------- weight transpose: W[K][N] -> fp16[N][K] ----------------
__global__ __launch_bounds__(256)
void tsplit_kernel(const float* __restrict__ W, __half* __restrict__ Th, int K, int N)
{
    __shared__ float t[32][33];
    int k0 = blockIdx.y * 32, n0 = blockIdx.x * 32;
    int tx = threadIdx.x & 31, ty = threadIdx.x >> 5;
#pragma unroll
    for (int i = 0; i < 4; i++)
        t[ty + i * 8][tx] = W[(size_t)(k0 + ty + i * 8) * N + n0 + tx];
    __syncthreads();
#pragma unroll
    for (int i = 0; i < 4; i++) {
        int n = ty + i * 8;
        Th[(size_t)(n0 + n) * K + k0 + tx] = __float2half_rn(t[tx][n]);
    }
}

// ---------------- fp16 two-limb warp-MMA GEMM (unchanged from round 8) ----------------
#define SMEM_GEMM 98304
#define BUFSZ 49152

__device__ __forceinline__ void load_tiles(
    const __half* Ah, const __half* Al, const __half* Bh,
    uint32_t base, int bm, int bn, int k0, int K, int tid)
{
#pragma unroll
    for (int i = 0; i < 4; i++) {
        int idx = tid + i * 256;
        int row = idx >> 3, seg = idx & 7;
        cp16(base + sw128(row * 128 + seg * 16),
             Ah + (size_t)(bm + row) * K + k0 + seg * 8);
    }
#pragma unroll
    for (int i = 0; i < 4; i++) {
        int idx = tid + i * 256;
        int row = idx >> 3, seg = idx & 7;
        cp16(base + 16384 + sw128(row * 128 + seg * 16),
             Al + (size_t)(bm + row) * K + k0 + seg * 8);
    }
#pragma unroll
    for (int i = 0; i < 4; i++) {
        int idx = tid + i * 256;
        int row = idx >> 3, seg = idx & 7;
        cp16(base + 32768 + sw128(row * 128 + seg * 16),
             Bh + (size_t)(bn + row) * K + k0 + seg * 8);
    }
}

__device__ __forceinline__ float gelu_tanh(float x) {
    float x3 = x * x * x;
    float t = tanhf(0.7978845608028654f * (x + 0.044715f * x3));
    return 0.5f * x * (1.f + t);
}

__global__ __launch_bounds__(256, 2)
void gemm_kernel(const __half* __restrict__ Ah, const __half* __restrict__ Al,
                 const __half* __restrict__ Bh,
                 const float* __restrict__ bias, float* __restrict__ Cf,
                 __half* __restrict__ Ch, __half* __restrict__ Cl,
                 int M, int N, int K, int act)
{
    extern __shared__ char smem[];
    const uint32_t sb = s2u(smem);
    const int tid = threadIdx.x;
    const int bm = blockIdx.y * 128, bn = blockIdx.x * 128;
    const int lane = tid & 31, wid = tid >> 5;
    const int wm = wid >> 2, wn = wid & 3;

    const int lrow = lane & 15;
    const uint32_t lcol = (uint32_t)(lane >> 4) * 16;
    uint32_t aOff[4], bOff[2];
#pragma unroll
    for (int mf = 0; mf < 4; mf++)
        aOff[mf] = (uint32_t)(wm * 64 + mf * 16 + lrow) * 128 + lcol;
#pragma unroll
    for (int np = 0; np < 2; np++)
        bOff[np] = (uint32_t)(wn * 32 + np * 16 + lrow) * 128 + lcol;

    float acc[4][4][4];
#pragma unroll
    for (int i = 0; i < 4; i++)
#pragma unroll
        for (int j = 0; j < 4; j++)
#pragma unroll
            for (int c = 0; c < 4; c++) acc[i][j][c] = 0.f;

    const int nk = K >> 6;
    load_tiles(Ah, Al, Bh, sb,         bm, bn, 0,  K, tid); CP_COMMIT();
    load_tiles(Ah, Al, Bh, sb + BUFSZ, bm, bn, 64, K, tid); CP_COMMIT();

    for (int it = 0; it < nk; it++) {
        const int b = it & 1;
        if (it + 2 <= nk) { CP_WAIT1(); } else { CP_WAIT0(); }
        __syncthreads();

        const uint32_t ahS = sb + (uint32_t)b * BUFSZ;
        const uint32_t alS = ahS + 16384;
        const uint32_t bhS = ahS + 32768;

#pragma unroll
        for (int ks = 0; ks < 4; ks++) {
            const uint32_t ko = (uint32_t)ks * 32;
            uint32_t af[4][4], bh[2][4];
#pragma unroll
            for (int np = 0; np < 2; np++)
                LDSM4(bh[np][0], bh[np][1], bh[np][2], bh[np][3], bhS + sw128(bOff[np] + ko));
#pragma unroll
            for (int mf = 0; mf < 4; mf++)
                LDSM4(af[mf][0], af[mf][1], af[mf][2], af[mf][3], ahS + sw128(aOff[mf] + ko));
#pragma unroll
            for (int mf = 0; mf < 4; mf++)
#pragma unroll
                for (int nf = 0; nf < 4; nf++)
                    MMA_F16(acc[mf][nf], af[mf], bh[nf >> 1][nf & 1], bh[nf >> 1][(nf & 1) + 2]);
#pragma unroll
            for (int mf = 0; mf < 4; mf++)
                LDSM4(af[mf][0], af[mf][1], af[mf][2], af[mf][3], alS + sw128(aOff[mf] + ko));
#pragma unroll
            for (int mf = 0; mf < 4; mf++)
#pragma unroll
                for (int nf = 0; nf < 4; nf++)
                    MMA_F16(acc[mf][nf], af[mf], bh[nf >> 1][nf & 1], bh[nf >> 1][(nf & 1) + 2]);
        }

        __syncthreads();
        if (it + 2 < nk) {
            load_tiles(Ah, Al, Bh, sb + (uint32_t)b * BUFSZ, bm, bn, (it + 2) * 64, K, tid);
            CP_COMMIT();
        }
    }

    const int g = lane >> 2, tg = lane & 3;
#pragma unroll
    for (int mf = 0; mf < 4; mf++) {
#pragma unroll
        for (int nf = 0; nf < 4; nf++) {
            const int col = bn + wn * 32 + nf * 8 + tg * 2;
            const float bxv = bias[col], byv = bias[col + 1];
#pragma unroll
            for (int half = 0; half < 2; half++) {
                const int row = bm + wm * 64 + mf * 16 + g + half * 8;
                float vx = acc[mf][nf][half * 2 + 0] + bxv;
                float vy = acc[mf][nf][half * 2 + 1] + byv;
                if (act) { vx = gelu_tanh(vx); vy = gelu_tanh(vy); }
                const size_t o = (size_t)row * N + col;
                if (Cf) { float2 f2 = make_float2(vx, vy); *(float2*)(Cf + o) = f2; }
                if (Ch) {
                    __half h0 = __float2half_rn(vx), h1 = __float2half_rn(vy);
                    *(__half2*)(Ch + o) = __halves2half2(h0, h1);
                    *(__half2*)(Cl + o) = __halves2half2(
                        __float2half_rn(vx - __half2float(h0)),
                        __float2half_rn(vy - __half2float(h1)));
                }
            }
        }
    }
}

// ---------------- tensor-core flash attention (MQA, causal) ----------------
// Block = (qtile 64, head, batch), 128 threads (4 warps x 16 q-rows).
// SMEM 48KB: stage Qh/Ql (2x16KB) then reuse as Kh(16KB)|Vth(16KB)|Vtl(16KB).
#define SMEM_ATTN 49152

__global__ __launch_bounds__(128)
void fattn_kernel(const float* __restrict__ qkv,
                  __half* __restrict__ ch, __half* __restrict__ cl)
{
    extern __shared__ char smem[];
    char* smc = smem;
    const uint32_t sb = s2u(smem);
    const int tid = threadIdx.x, lane = tid & 31, wid = tid >> 5;
    const int qb = blockIdx.x * 64;
    const int h  = blockIdx.y;
    const int b  = blockIdx.z;
    const int lrow = lane & 15;
    const uint32_t lcol = (uint32_t)(lane >> 4) * 16;
    const int g = lane >> 2, tg = lane & 3;

    // ---- stage Q (scaled, two fp16 limbs) into panels ----
    {
        const float* qsrc = qkv + (size_t)(b * SS + qb) * QKN + h * HDIM;
#pragma unroll
        for (int i = 0; i < 16; i++) {
            int idx = tid + i * 128;
            int r = idx >> 5, ds = idx & 31;
            float4 v = *(const float4*)(qsrc + (size_t)r * QKN + ds * 4);
            float s0 = v.x * ATT_SCALE, s1 = v.y * ATT_SCALE;
            float s2 = v.z * ATT_SCALE, s3 = v.w * ATT_SCALE;
            __half h0 = __float2half_rn(s0), h1 = __float2half_rn(s1);
            __half h2 = __float2half_rn(s2), h3 = __float2half_rn(s3);
            uint32_t off = (uint32_t)(ds >> 4) * 8192 +
                           sw128((uint32_t)r * 128 + (ds & 15) * 8);
            uint2 wh;
            { __half2 t0 = __halves2half2(h0, h1), t1 = __halves2half2(h2, h3);
              wh.x = *(uint32_t*)&t0; wh.y = *(uint32_t*)&t1; }
            *(uint2*)(smc + off) = wh;
            uint2 wl;
            { __half2 t0 = __halves2half2(__float2half_rn(s0 - __half2float(h0)),
                                          __float2half_rn(s1 - __half2float(h1)));
              __half2 t1 = __halves2half2(__float2half_rn(s2 - __half2float(h2)),
                                          __float2half_rn(s3 - __half2float(h3)));
              wl.x = *(uint32_t*)&t0; wl.y = *(uint32_t*)&t1; }
            *(uint2*)(smc + 16384 + off) = wl;
        }
    }
    __syncthreads();

    // ---- Q fragments (kept in registers across all chunks) ----
    uint32_t qf[2][8][4];
    {
        uint32_t qOff = (uint32_t)(wid * 16 + lrow) * 128 + lcol;
#pragma unroll
        for (int ks = 0; ks < 8; ks++) {
            uint32_t a = sb + (uint32_t)(ks >> 2) * 8192 + sw128(qOff + (ks & 3) * 32);
            LDSM4(qf[0][ks][0], qf[0][ks][1], qf[0][ks][2], qf[0][ks][3], a);
            LDSM4(qf[1][ks][0], qf[1][ks][1], qf[1][ks][2], qf[1][ks][3], a + 16384);
        }
    }
    __syncthreads();

    float oacc[16][4];
#pragma unroll
    for (int i = 0; i < 16; i++)
#pragma unroll
        for (int c = 0; c < 4; c++) oacc[i][c] = 0.f;
    float m0 = -1e30f, m1 = -1e30f, l0 = 0.f, l1 = 0.f;

    const int nchunks = qb / 64 + 1;
    const float* kvb = qkv + (size_t)(b * SS) * QKN + DD;

    for (int kc = 0; kc < nchunks; kc++) {
        // ---- K chunk -> Kh panels (coalesced reads, conflict-free stores) ----
#pragma unroll
        for (int i = 0; i < 16; i++) {
            int idx = tid + i * 128;
            int key = idx >> 5, ds = idx & 31;
            float4 v = *(const float4*)(kvb + (size_t)(kc * 64 + key) * QKN + ds * 4);
            uint32_t off = (uint32_t)(ds >> 4) * 8192 +
                           sw128((uint32_t)key * 128 + (ds & 15) * 8);
            uint2 wh;
            { __half2 t0 = __halves2half2(__float2half_rn(v.x), __float2half_rn(v.y));
              __half2 t1 = __halves2half2(__float2half_rn(v.z), __float2half_rn(v.w));
              wh.x = *(uint32_t*)&t0; wh.y = *(uint32_t*)&t1; }
            *(uint2*)(smc + off) = wh;
        }
        // ---- V chunk -> Vth/Vtl transposed [dim][key] ----
#pragma unroll
        for (int i = 0; i < 16; i++) {
            int idx = tid + i * 128;
            int key = idx & 63, ds = idx >> 6;
            float4 v = *(const float4*)(kvb + (size_t)(kc * 64 + key) * QKN + HDIM + ds * 4);
            const float* vp = &v.x;
#pragma unroll
            for (int j = 0; j < 4; j++) {
                int d = ds * 4 + j;
                float f = vp[j];
                __half hh = __float2half_rn(f);
                uint32_t off = sw128((uint32_t)d * 128 + key * 2);
                *(__half*)(smc + 16384 + off) = hh;
                *(__half*)(smc + 32768 + off) = __float2half_rn(f - __half2float(hh));
            }
        }
        __syncthreads();

        // ---- S = (Qh+Ql) @ Kh^T ----
        float sacc[8][4];
#pragma unroll
        for (int i = 0; i < 8; i++)
#pragma unroll
            for (int c = 0; c < 4; c++) sacc[i][c] = 0.f;
#pragma unroll
        for (int ks = 0; ks < 8; ks++) {
            uint32_t kb4[4][4];
#pragma unroll
            for (int np = 0; np < 4; np++)
                LDSM4(kb4[np][0], kb4[np][1], kb4[np][2], kb4[np][3],
                      sb + (uint32_t)(ks >> 2) * 8192 +
                      sw128((uint32_t)(np * 16 + lrow) * 128 + lcol + (ks & 3) * 32));
#pragma unroll
            for (int limb = 0; limb < 2; limb++)
#pragma unroll
                for (int nf = 0; nf < 8; nf++)
                    MMA_F16(sacc[nf], qf[limb][ks],
                            kb4[nf >> 1][nf & 1], kb4[nf >> 1][(nf & 1) + 2]);
        }

        // ---- causal mask on diagonal chunk ----
        if (kc * 64 == qb) {
            const int r0 = wid * 16 + g, r1 = r0 + 8;
#pragma unroll
            for (int nf = 0; nf < 8; nf++) {
                int c0 = nf * 8 + tg * 2;
                if (c0 > r0)     sacc[nf][0] = -1e30f;
                if (c0 + 1 > r0) sacc[nf][1] = -1e30f;
                if (c0 > r1)     sacc[nf][2] = -1e30f;
                if (c0 + 1 > r1) sacc[nf][3] = -1e30f;
            }
        }

        // ---- online softmax ----
        float mx0 = m0, mx1 = m1;
#pragma unroll
        for (int nf = 0; nf < 8; nf++) {
            mx0 = fmaxf(mx0, fmaxf(sacc[nf][0], sacc[nf][1]));
            mx1 = fmaxf(mx1, fmaxf(sacc[nf][2], sacc[nf][3]));
        }
        mx0 = fmaxf(mx0, __shfl_xor_sync(0xffffffffu, mx0, 1));
        mx0 = fmaxf(mx0, __shfl_xor_sync(0xffffffffu, mx0, 2));
        mx1 = fmaxf(mx1, __shfl_xor_sync(0xffffffffu, mx1, 1));
        mx1 = fmaxf(mx1, __shfl_xor_sync(0xffffffffu, mx1, 2));
        float sc0 = __expf(m0 - mx0), sc1 = __expf(m1 - mx1);
        m0 = mx0; m1 = mx1;
        l0 *= sc0; l1 *= sc1;
#pragma unroll
        for (int nf = 0; nf < 16; nf++) {
            oacc[nf][0] *= sc0; oacc[nf][1] *= sc0;
            oacc[nf][2] *= sc1; oacc[nf][3] *= sc1;
        }
        uint32_t pp[8][2];
#pragma unroll
        for (int nf = 0; nf < 8; nf++) {
            float e0 = __expf(sacc[nf][0] - mx0), e1 = __expf(sacc[nf][1] - mx0);
            float e2 = __expf(sacc[nf][2] - mx1), e3 = __expf(sacc[nf][3] - mx1);
            l0 += e0 + e1; l1 += e2 + e3;
            pp[nf][0] = packh2(e0, e1);
            pp[nf][1] = packh2(e2, e3);
        }

        // ---- O += P @ (Vh + Vl) ----
#pragma unroll
        for (int ks2 = 0; ks2 < 4; ks2++) {
            uint32_t pa[4] = { pp[2 * ks2][0], pp[2 * ks2][1],
                               pp[2 * ks2 + 1][0], pp[2 * ks2 + 1][1] };
#pragma unroll
            for (int limb = 0; limb < 2; limb++) {
                uint32_t vbase = sb + 16384 + (uint32_t)limb * 16384;
#pragma unroll
                for (int np = 0; np < 8; np++) {
                    uint32_t vb4[4];
                    LDSM4(vb4[0], vb4[1], vb4[2], vb4[3],
                          vbase + sw128((uint32_t)(np * 16 + lrow) * 128 + lcol + ks2 * 32));
                    MMA_F16(oacc[2 * np],     pa, vb4[0], vb4[2]);
                    MMA_F16(oacc[2 * np + 1], pa, vb4[1], vb4[3]);
                }
            }
        }
        __syncthreads();
    }

    // ---- epilogue: normalize, write ctx as fp16 hi/lo ----
    l0 += __shfl_xor_sync(0xffffffffu, l0, 1);
    l0 += __shfl_xor_sync(0xffffffffu, l0, 2);
    l1 += __shfl_xor_sync(0xffffffffu, l1, 1);
    l1 += __shfl_xor_sync(0xffffffffu, l1, 2);
    const float inv0 = 1.f / l0, inv1 = 1.f / l1;
    const size_t row0 = (size_t)(b * SS + qb + wid * 16 + g);
#pragma unroll
    for (int nf = 0; nf < 16; nf++) {
        const int col = h * HDIM + nf * 8 + tg * 2;
        {
            float vx = oacc[nf][0] * inv0, vy = oacc[nf][1] * inv0;
            __half h0 = __float2half_rn(vx), h1 = __float2half_rn(vy);
            const size_t o = row0 * DD + col;
            *(__half2*)(ch + o) = __halves2half2(h0, h1);
            *(__half2*)(cl + o) = __halves2half2(
                __float2half_rn(vx - __half2float(h0)),
                __float2half_rn(vy - __half2float(h1)));
        }
        {
            float vx = oacc[nf][2] * inv1, vy = oacc[nf][3] * inv1;
            __half h0 = __float2half_rn(vx), h1 = __float2half_rn(vy);
            const size_t o = (row0 + 8) * DD + col;
            *(__half2*)(ch + o) = __halves2half2(h0, h1);
            *(__half2*)(cl + o) = __halves2half2(
                __float2half_rn(vx - __half2float(h0)),
                __float2half_rn(vy - __half2float(h1)));
        }
    }
}

// ---------------- launch ----------------
extern "C" void kernel_launch(void* const* d_in, const int* in_sizes, int n_in,
                              void* d_out, int out_size)
{
    const int*   ids      = (const int*)  d_in[0];
    const int*   pos      = (const int*)  d_in[1];
    const float* wte      = (const float*)d_in[2];
    const float* wpe      = (const float*)d_in[3];
    const float* c_attn_w = (const float*)d_in[4];
    const float* c_attn_b = (const float*)d_in[5];
    const float* c_proj_w = (const float*)d_in[6];
    const float* c_proj_b = (const float*)d_in[7];
    const float* ln1_w    = (const float*)d_in[8];
    const float* ln1_b    = (const float*)d_in[9];
    const float* ln2_w    = (const float*)d_in[10];
    const float* ln2_b    = (const float*)d_in[11];
    const float* fc_w     = (const float*)d_in[12];
    const float* fc_b     = (const float*)d_in[13];
    const float* mp_w     = (const float*)d_in[14];
    const float* mp_b     = (const float*)d_in[15];
    const float* lnf_w    = (const float*)d_in[16];
    const float* lnf_b    = (const float*)d_in[17];
    float* out = (float*)d_out;

    float *h, *res, *res2, *qkv, *attn;
    __half *xh, *xl, *ch, *cl, *fh, *fl, *wq, *wp, *wf, *wm;
    cudaGetSymbolAddress((void**)&h,    g_h);
    cudaGetSymbolAddress((void**)&res,  g_res);
    cudaGetSymbolAddress((void**)&res2, g_res2);
    cudaGetSymbolAddress((void**)&qkv,  g_qkv);
    cudaGetSymbolAddress((void**)&attn, g_attn);
    cudaGetSymbolAddress((void**)&xh,   g_xh);
    cudaGetSymbolAddress((void**)&xl,   g_xl);
    cudaGetSymbolAddress((void**)&ch,   g_ch);
    cudaGetSymbolAddress((void**)&cl,   g_cl);
    cudaGetSymbolAddress((void**)&fh,   g_fh);
    cudaGetSymbolAddress((void**)&fl,   g_fl);
    cudaGetSymbolAddress((void**)&wq,   g_wq);
    cudaGetSymbolAddress((void**)&wp,   g_wp);
    cudaGetSymbolAddress((void**)&wf,   g_wf);
    cudaGetSymbolAddress((void**)&wm,   g_wm);

    cudaFuncSetAttribute(gemm_kernel,  cudaFuncAttributeMaxDynamicSharedMemorySize, SMEM_GEMM);
    cudaFuncSetAttribute(fattn_kernel, cudaFuncAttributeMaxDynamicSharedMemorySize, SMEM_ATTN);

    const dim3 agrid(SS / 64, HH, BB);

    // Launch order: index 5 is fattn (ncu -s 5 -c 1 captures it).
    embed_kernel<<<(TT * DD + 255) / 256, 256>>>(ids, pos, wte, wpe, h);       // 0
    tsplit_kernel<<<dim3(QKN / 32, DD / 32), 256>>>(c_attn_w, wq, DD, QKN);    // 1
    tsplit_kernel<<<dim3(DD / 32, DD / 32), 256>>>(c_proj_w, wp, DD, DD);      // 2
    ln_kernel<<<TT, 256>>>(h, nullptr, ln1_w, ln1_b, res, nullptr, xh, xl);    // 3
    gemm_kernel<<<dim3(QKN / 128, TT / 128), 256, SMEM_GEMM>>>(                // 4
        xh, xl, wq, c_attn_b, qkv, nullptr, nullptr, TT, QKN, DD, 0);
    fattn_kernel<<<agrid, 128, SMEM_ATTN>>>(qkv, ch, cl);                      // 5 <- profiled
    tsplit_kernel<<<dim3(FFN / 32, DD / 32), 256>>>(fc_w, wf, DD, FFN);        // 6
    tsplit_kernel<<<dim3(DD / 32, FFN / 32), 256>>>(mp_w, wm, FFN, DD);        // 7
    gemm_kernel<<<dim3(DD / 128, TT / 128), 256, SMEM_GEMM>>>(
        ch, cl, wp, c_proj_b, attn, nullptr, nullptr, TT, DD, DD, 0);
    ln_kernel<<<TT, 256>>>(attn, res, ln2_w, ln2_b, res2, nullptr, xh, xl);
    gemm_kernel<<<dim3(FFN / 128, TT / 128), 256, SMEM_GEMM>>>(
        xh, xl, wf, fc_b, nullptr, fh, fl, TT, FFN, DD, 1);
    gemm_kernel<<<dim3(DD / 128, TT / 128), 256, SMEM_GEMM>>>(
        fh, fl, wm, mp_b, h, nullptr, nullptr, TT, DD, FFN, 0);

    // remaining layers
    for (int l = 1; l < NL; l++) {
        tsplit_kernel<<<dim3(QKN / 32, DD / 32), 256>>>(
            c_attn_w + (size_t)l * DD * QKN, wq + (size_t)l * QKN * DD, DD, QKN);
        tsplit_kernel<<<dim3(DD / 32, DD / 32), 256>>>(
            c_proj_w + (size_t)l * DD * DD, wp + (size_t)l * DD * DD, DD, DD);
        tsplit_kernel<<<dim3(FFN / 32, DD / 32), 256>>>(
            fc_w + (size_t)l * DD * FFN, wf + (size_t)l * FFN * DD, DD, FFN);
        tsplit_kernel<<<dim3(DD / 32, FFN / 32), 256>>>(
            mp_w + (size_t)l * FFN * DD, wm + (size_t)l * DD * FFN, FFN, DD);

        ln_kernel<<<TT, 256>>>(h, res2, ln1_w + (size_t)l * DD, ln1_b + (size_t)l * DD,
                               res, nullptr, xh, xl);
        gemm_kernel<<<dim3(QKN / 128, TT / 128), 256, SMEM_GEMM>>>(
            xh, xl, wq + (size_t)l * QKN * DD,
            c_attn_b + (size_t)l * QKN, qkv, nullptr, nullptr, TT, QKN, DD, 0);
        fattn_kernel<<<agrid, 128, SMEM_ATTN>>>(qkv, ch, cl);
        gemm_kernel<<<dim3(DD / 128, TT / 128), 256, SMEM_GEMM>>>(
            ch, cl, wp + (size_t)l * DD * DD,
            c_proj_b + (size_t)l * DD, attn, nullptr, nullptr, TT, DD, DD, 0);
        ln_kernel<<<TT, 256>>>(attn, res, ln2_w + (size_t)l * DD, ln2_b + (size_t)l * DD,
                               res2, nullptr, xh, xl);
        gemm_kernel<<<dim3(FFN / 128, TT / 128), 256, SMEM_GEMM>>>(
            xh, xl, wf + (size_t)l * FFN * DD,
            fc_b + (size_t)l * FFN, nullptr, fh, fl, TT, FFN, DD, 1);
        gemm_kernel<<<dim3(DD / 128, TT / 128), 256, SMEM_GEMM>>>(
            fh, fl, wm + (size_t)l * DD * FFN,
            mp_b + (size_t)l * DD, h, nullptr, nullptr, TT, DD, FFN, 0);
    }

    ln_kernel<<<TT, 256>>>(h, res2, lnf_w, lnf_b, nullptr, out, nullptr, nullptr);
}

// round 10
// speedup vs baseline: 4.0401x; 1.6257x over previous
#include <cuda_runtime.h>
#include <cuda_fp16.h>
#include <math.h>
#include <stdint.h>

// ---------------- model constants ----------------
#define TT   2048
#define DD   2048
#define HH   16
#define HDIM 128
#define SS   1024
#define BB   2
#define FFN  8192
#define QKN  2304
#define NL   2
#define LN_EPS 1e-5f
#define ATT_SCALE 0.08838834764831845f

// ---------------- fp32 scratch ----------------
__device__ float g_h   [TT * DD];
__device__ float g_res [TT * DD];
__device__ float g_res2[TT * DD];
__device__ float g_qkv [TT * QKN];
__device__ float g_attn[TT * DD];

// ---------------- fp16 activations (single limb) ----------------
__device__ __align__(16) __half g_xh[TT*DD];
__device__ __align__(16) __half g_ch[TT*DD];
__device__ __align__(16) __half g_fh[TT*FFN];

// transposed weights [N][K], fp16
__device__ __align__(16) __half g_wq[NL*QKN*DD];
__device__ __align__(16) __half g_wp[NL*DD*DD];
__device__ __align__(16) __half g_wf[NL*FFN*DD];
__device__ __align__(16) __half g_wm[NL*DD*FFN];

// ---------------- PTX helpers (plain sm_80 features) ----------------
__device__ __forceinline__ uint32_t s2u(const void* p) {
    uint32_t a;
    asm("{ .reg .u64 t; cvta.to.shared.u64 t, %1; cvt.u32.u64 %0, t; }" : "=r"(a) : "l"(p));
    return a;
}
__device__ __forceinline__ uint32_t sw128(uint32_t o) { return o ^ ((o >> 3) & 0x70); }
__device__ __forceinline__ void cp16(uint32_t d, const void* s) {
    asm volatile("cp.async.cg.shared.global [%0], [%1], 16;" :: "r"(d), "l"(s));
}
#define CP_COMMIT() asm volatile("cp.async.commit_group;" ::: "memory")
#define CP_WAIT1()  asm volatile("cp.async.wait_group 1;" ::: "memory")
#define CP_WAIT0()  asm volatile("cp.async.wait_group 0;" ::: "memory")

#define LDSM4(R0, R1, R2, R3, ADDR) \
    asm volatile("ldmatrix.sync.aligned.m8n8.x4.shared.b16 {%0,%1,%2,%3}, [%4];" \
        : "=r"(R0), "=r"(R1), "=r"(R2), "=r"(R3) : "r"(ADDR))

#define MMA_F16(D, A, B0, B1) \
    asm volatile("mma.sync.aligned.m16n8k16.row.col.f32.f16.f16.f32 " \
        "{%0,%1,%2,%3}, {%4,%5,%6,%7}, {%8,%9}, {%0,%1,%2,%3};" \
        : "+f"((D)[0]), "+f"((D)[1]), "+f"((D)[2]), "+f"((D)[3]) \
        : "r"((A)[0]), "r"((A)[1]), "r"((A)[2]), "r"((A)[3]), "r"(B0), "r"(B1))

__device__ __forceinline__ uint32_t packh2(float a, float b) {
    __half2 t = __halves2half2(__float2half_rn(a), __float2half_rn(b));
    return *(uint32_t*)&t;
}

// ---------------- embed ----------------
__global__ void embed_kernel(const int* __restrict__ ids, const int* __restrict__ pos,
                             const float* __restrict__ wte, const float* __restrict__ wpe,
                             float* __restrict__ out)
{
    int idx = blockIdx.x * blockDim.x + threadIdx.x;
    if (idx >= TT * DD) return;
    int t = idx >> 11, d = idx & (DD - 1);
    out[idx] = wte[(size_t)ids[t] * DD + d] + wpe[(size_t)pos[t] * DD + d];
}

// ---------------- fused residual-add + LayerNorm (+ fp16 out) ----------------
__global__ __launch_bounds__(256)
void ln_kernel(const float* __restrict__ a, const float* __restrict__ r,
               const float* __restrict__ g, const float* __restrict__ b,
               float* __restrict__ res_out, float* __restrict__ xf,
               __half* __restrict__ xh)
{
    const int t = blockIdx.x;
    const size_t base = (size_t)t * DD;
    float v[8];
    float s = 0.f, sq = 0.f;
#pragma unroll
    for (int i = 0; i < 8; i++) {
        int idx = threadIdx.x + i * 256;
        float val = a[base + idx];
        if (r) val += r[base + idx];
        v[i] = val; s += val; sq += val * val;
    }
    int lane = threadIdx.x & 31, wid = threadIdx.x >> 5;
#pragma unroll
    for (int o = 16; o; o >>= 1) {
        s  += __shfl_xor_sync(0xffffffffu, s,  o);
        sq += __shfl_xor_sync(0xffffffffu, sq, o);
    }
    __shared__ float shs[8], shq[8], smean, srstd;
    if (lane == 0) { shs[wid] = s; shq[wid] = sq; }
    __syncthreads();
    if (threadIdx.x == 0) {
        float ts = 0.f, tq = 0.f;
#pragma unroll
        for (int i = 0; i < 8; i++) { ts += shs[i]; tq += shq[i]; }
        float mean = ts * (1.f / DD);
        float var  = tq * (1.f / DD) - mean * mean;
        smean = mean; srstd = rsqrtf(var + LN_EPS);
    }
    __syncthreads();
    float mean = smean, rstd = srstd;
#pragma unroll
    for (int i = 0; i < 8; i++) {
        int idx = threadIdx.x + i * 256;
        if (res_out) res_out[base + idx] = v[i];
        float y = (v[i] - mean) * rstd * g[idx] + b[idx];
        if (xf) xf[base + idx] = y;
        if (xh) xh[base + idx] = __float2half_rn(y);
    }
}

// ---------------- weight transpose: W[K][N] -> fp16[N][K] ----------------
__global__ __launch_bounds__(256)
void tsplit_kernel(const float* __restrict__ W, __half* __restrict__ Th, int K, int N)
{
    __shared__ float t[32][33];
    int k0 = blockIdx.y * 32, n0 = blockIdx.x * 32;
    int tx = threadIdx.x & 31, ty = threadIdx.x >> 5;
#pragma unroll
    for (int i = 0; i < 4; i++)
        t[ty + i * 8][tx] = W[(size_t)(k0 + ty + i * 8) * N + n0 + tx];
    __syncthreads();
#pragma unroll
    for (int i = 0; i < 4; i++) {
        int n = ty + i * 8;
        Th[(size_t)(n0 + n) * K + k0 + tx] = __float2half_rn(t[tx][n]);
    }
}

// ---------------- pure fp16 warp-MMA GEMM (single pass) ----------------
// C = Ah @ Bh^T + bias. CTA 128x128, K-chunk 64, 8 warps (2x4), warp 64x32.
// Buffer (32KB): Ah 16KB | Bh 16KB. Double buffered = 64KB, 2 CTAs/SM.
#define SMEM_GEMM 65536
#define BUFSZ 32768

__device__ __forceinline__ void load_tiles(
    const __half* Ah, const __half* Bh,
    uint32_t base, int bm, int bn, int k0, int K, int tid)
{
#pragma unroll
    for (int i = 0; i < 4; i++) {
        int idx = tid + i * 256;
        int row = idx >> 3, seg = idx & 7;
        cp16(base + sw128(row * 128 + seg * 16),
             Ah + (size_t)(bm + row) * K + k0 + seg * 8);
    }
#pragma unroll
    for (int i = 0; i < 4; i++) {
        int idx = tid + i * 256;
        int row = idx >> 3, seg = idx & 7;
        cp16(base + 16384 + sw128(row * 128 + seg * 16),
             Bh + (size_t)(bn + row) * K + k0 + seg * 8);
    }
}

__device__ __forceinline__ float gelu_tanh(float x) {
    float x3 = x * x * x;
    float t = tanhf(0.7978845608028654f * (x + 0.044715f * x3));
    return 0.5f * x * (1.f + t);
}

__global__ __launch_bounds__(256, 2)
void gemm_kernel(const __half* __restrict__ Ah, const __half* __restrict__ Bh,
                 const float* __restrict__ bias, float* __restrict__ Cf,
                 __half* __restrict__ Ch,
                 int M, int N, int K, int act)
{
    extern __shared__ char smem[];
    const uint32_t sb = s2u(smem);
    const int tid = threadIdx.x;
    const int bm = blockIdx.y * 128, bn = blockIdx.x * 128;
    const int lane = tid & 31, wid = tid >> 5;
    const int wm = wid >> 2, wn = wid & 3;

    const int lrow = lane & 15;
    const uint32_t lcol = (uint32_t)(lane >> 4) * 16;
    uint32_t aOff[4], bOff[2];
#pragma unroll
    for (int mf = 0; mf < 4; mf++)
        aOff[mf] = (uint32_t)(wm * 64 + mf * 16 + lrow) * 128 + lcol;
#pragma unroll
    for (int np = 0; np < 2; np++)
        bOff[np] = (uint32_t)(wn * 32 + np * 16 + lrow) * 128 + lcol;

    float acc[4][4][4];
#pragma unroll
    for (int i = 0; i < 4; i++)
#pragma unroll
        for (int j = 0; j < 4; j++)
#pragma unroll
            for (int c = 0; c < 4; c++) acc[i][j][c] = 0.f;

    const int nk = K >> 6;
    load_tiles(Ah, Bh, sb,         bm, bn, 0,  K, tid); CP_COMMIT();
    load_tiles(Ah, Bh, sb + BUFSZ, bm, bn, 64, K, tid); CP_COMMIT();

    for (int it = 0; it < nk; it++) {
        const int b = it & 1;
        if (it + 2 <= nk) { CP_WAIT1(); } else { CP_WAIT0(); }
        __syncthreads();

        const uint32_t ahS = sb + (uint32_t)b * BUFSZ;
        const uint32_t bhS = ahS + 16384;

#pragma unroll
        for (int ks = 0; ks < 4; ks++) {
            const uint32_t ko = (uint32_t)ks * 32;
            uint32_t af[4][4], bh[2][4];
#pragma unroll
            for (int np = 0; np < 2; np++)
                LDSM4(bh[np][0], bh[np][1], bh[np][2], bh[np][3], bhS + sw128(bOff[np] + ko));
#pragma unroll
            for (int mf = 0; mf < 4; mf++)
                LDSM4(af[mf][0], af[mf][1], af[mf][2], af[mf][3], ahS + sw128(aOff[mf] + ko));
#pragma unroll
            for (int mf = 0; mf < 4; mf++)
#pragma unroll
                for (int nf = 0; nf < 4; nf++)
                    MMA_F16(acc[mf][nf], af[mf], bh[nf >> 1][nf & 1], bh[nf >> 1][(nf & 1) + 2]);
        }

        __syncthreads();
        if (it + 2 < nk) {
            load_tiles(Ah, Bh, sb + (uint32_t)b * BUFSZ, bm, bn, (it + 2) * 64, K, tid);
            CP_COMMIT();
        }
    }

    const int g = lane >> 2, tg = lane & 3;
#pragma unroll
    for (int mf = 0; mf < 4; mf++) {
#pragma unroll
        for (int nf = 0; nf < 4; nf++) {
            const int col = bn + wn * 32 + nf * 8 + tg * 2;
            const float bxv = bias[col], byv = bias[col + 1];
#pragma unroll
            for (int half = 0; half < 2; half++) {
                const int row = bm + wm * 64 + mf * 16 + g + half * 8;
                float vx = acc[mf][nf][half * 2 + 0] + bxv;
                float vy = acc[mf][nf][half * 2 + 1] + byv;
                if (act) { vx = gelu_tanh(vx); vy = gelu_tanh(vy); }
                const size_t o = (size_t)row * N + col;
                if (Cf) { float2 f2 = make_float2(vx, vy); *(float2*)(Cf + o) = f2; }
                if (Ch) *(__half2*)(Ch + o) =
                    __halves2half2(__float2half_rn(vx), __float2half_rn(vy));
            }
        }
    }
}

// ---------------- tensor-core flash attention (MQA, causal, fp16) ----------------
// Block = (qtile 64, head, batch), 128 threads (4 warps x 16 q-rows).
// SMEM 32KB: Q panels (16KB) then reuse as Kh(16KB) | Vth(16KB).
#define SMEM_ATTN 32768

__global__ __launch_bounds__(128)
void fattn_kernel(const float* __restrict__ qkv, __half* __restrict__ ch)
{
    extern __shared__ char smem[];
    char* smc = smem;
    const uint32_t sb = s2u(smem);
    const int tid = threadIdx.x, lane = tid & 31, wid = tid >> 5;
    const int qb = blockIdx.x * 64;
    const int h  = blockIdx.y;
    const int b  = blockIdx.z;
    const int lrow = lane & 15;
    const uint32_t lcol = (uint32_t)(lane >> 4) * 16;
    const int g = lane >> 2, tg = lane & 3;

    // ---- stage Q (scaled fp16) into two 8KB panels ----
    {
        const float* qsrc = qkv + (size_t)(b * SS + qb) * QKN + h * HDIM;
#pragma unroll
        for (int i = 0; i < 16; i++) {
            int idx = tid + i * 128;
            int r = idx >> 5, ds = idx & 31;
            float4 v = *(const float4*)(qsrc + (size_t)r * QKN + ds * 4);
            uint32_t off = (uint32_t)(ds >> 4) * 8192 +
                           sw128((uint32_t)r * 128 + (ds & 15) * 8);
            uint2 wh;
            { __half2 t0 = __halves2half2(__float2half_rn(v.x * ATT_SCALE),
                                          __float2half_rn(v.y * ATT_SCALE));
              __half2 t1 = __halves2half2(__float2half_rn(v.z * ATT_SCALE),
                                          __float2half_rn(v.w * ATT_SCALE));
              wh.x = *(uint32_t*)&t0; wh.y = *(uint32_t*)&t1; }
            *(uint2*)(smc + off) = wh;
        }
    }
    __syncthreads();

    // ---- Q fragments (registers, all chunks) ----
    uint32_t qf[8][4];
    {
        uint32_t qOff = (uint32_t)(wid * 16 + lrow) * 128 + lcol;
#pragma unroll
        for (int ks = 0; ks < 8; ks++) {
            uint32_t a = sb + (uint32_t)(ks >> 2) * 8192 + sw128(qOff + (ks & 3) * 32);
            LDSM4(qf[ks][0], qf[ks][1], qf[ks][2], qf[ks][3], a);
        }
    }
    __syncthreads();

    float oacc[16][4];
#pragma unroll
    for (int i = 0; i < 16; i++)
#pragma unroll
        for (int c = 0; c < 4; c++) oacc[i][c] = 0.f;
    float m0 = -1e30f, m1 = -1e30f, l0 = 0.f, l1 = 0.f;

    const int nchunks = qb / 64 + 1;
    const float* kvb = qkv + (size_t)(b * SS) * QKN + DD;

    for (int kc = 0; kc < nchunks; kc++) {
        // ---- K chunk -> panels at 0 / 8192 ----
#pragma unroll
        for (int i = 0; i < 16; i++) {
            int idx = tid + i * 128;
            int key = idx >> 5, ds = idx & 31;
            float4 v = *(const float4*)(kvb + (size_t)(kc * 64 + key) * QKN + ds * 4);
            uint32_t off = (uint32_t)(ds >> 4) * 8192 +
                           sw128((uint32_t)key * 128 + (ds & 15) * 8);
            uint2 wh;
            { __half2 t0 = __halves2half2(__float2half_rn(v.x), __float2half_rn(v.y));
              __half2 t1 = __halves2half2(__float2half_rn(v.z), __float2half_rn(v.w));
              wh.x = *(uint32_t*)&t0; wh.y = *(uint32_t*)&t1; }
            *(uint2*)(smc + off) = wh;
        }
        // ---- V chunk -> Vth transposed [dim][key] at 16384 ----
#pragma unroll
        for (int i = 0; i < 16; i++) {
            int idx = tid + i * 128;
            int key = idx & 63, ds = idx >> 6;
            float4 v = *(const float4*)(kvb + (size_t)(kc * 64 + key) * QKN + HDIM + ds * 4);
            const float* vp = &v.x;
#pragma unroll
            for (int j = 0; j < 4; j++) {
                int d = ds * 4 + j;
                *(__half*)(smc + 16384 + sw128((uint32_t)d * 128 + key * 2)) =
                    __float2half_rn(vp[j]);
            }
        }
        __syncthreads();

        // ---- S = Q @ K^T ----
        float sacc[8][4];
#pragma unroll
        for (int i = 0; i < 8; i++)
#pragma unroll
            for (int c = 0; c < 4; c++) sacc[i][c] = 0.f;
#pragma unroll
        for (int ks = 0; ks < 8; ks++) {
            uint32_t kb4[4][4];
#pragma unroll
            for (int np = 0; np < 4; np++)
                LDSM4(kb4[np][0], kb4[np][1], kb4[np][2], kb4[np][3],
                      sb + (uint32_t)(ks >> 2) * 8192 +
                      sw128((uint32_t)(np * 16 + lrow) * 128 + lcol + (ks & 3) * 32));
#pragma unroll
            for (int nf = 0; nf < 8; nf++)
                MMA_F16(sacc[nf], qf[ks],
                        kb4[nf >> 1][nf & 1], kb4[nf >> 1][(nf & 1) + 2]);
        }

        // ---- causal mask on diagonal chunk ----
        if (kc * 64 == qb) {
            const int r0 = wid * 16 + g, r1 = r0 + 8;
#pragma unroll
            for (int nf = 0; nf < 8; nf++) {
                int c0 = nf * 8 + tg * 2;
                if (c0 > r0)     sacc[nf][0] = -1e30f;
                if (c0 + 1 > r0) sacc[nf][1] = -1e30f;
                if (c0 > r1)     sacc[nf][2] = -1e30f;
                if (c0 + 1 > r1) sacc[nf][3] = -1e30f;
            }
        }

        // ---- online softmax ----
        float mx0 = m0, mx1 = m1;
#pragma unroll
        for (int nf = 0; nf < 8; nf++) {
            mx0 = fmaxf(mx0, fmaxf(sacc[nf][0], sacc[nf][1]));
            mx1 = fmaxf(mx1, fmaxf(sacc[nf][2], sacc[nf][3]));
        }
        mx0 = fmaxf(mx0, __shfl_xor_sync(0xffffffffu, mx0, 1));
        mx0 = fmaxf(mx0, __shfl_xor_sync(0xffffffffu, mx0, 2));
        mx1 = fmaxf(mx1, __shfl_xor_sync(0xffffffffu, mx1, 1));
        mx1 = fmaxf(mx1, __shfl_xor_sync(0xffffffffu, mx1, 2));
        float sc0 = __expf(m0 - mx0), sc1 = __expf(m1 - mx1);
        m0 = mx0; m1 = mx1;
        l0 *= sc0; l1 *= sc1;
#pragma unroll
        for (int nf = 0; nf < 16; nf++) {
            oacc[nf][0] *= sc0; oacc[nf][1] *= sc0;
            oacc[nf][2] *= sc1; oacc[nf][3] *= sc1;
        }
        uint32_t pp[8][2];
#pragma unroll
        for (int nf = 0; nf < 8; nf++) {
            float e0 = __expf(sacc[nf][0] - mx0), e1 = __expf(sacc[nf][1] - mx0);
            float e2 = __expf(sacc[nf][2] - mx1), e3 = __expf(sacc[nf][3] - mx1);
            l0 += e0 + e1; l1 += e2 + e3;
            pp[nf][0] = packh2(e0, e1);
            pp[nf][1] = packh2(e2, e3);
        }

        // ---- O += P @ V ----
#pragma unroll
        for (int ks2 = 0; ks2 < 4; ks2++) {
            uint32_t pa[4] = { pp[2 * ks2][0], pp[2 * ks2][1],
                               pp[2 * ks2 + 1][0], pp[2 * ks2 + 1][1] };
#pragma unroll
            for (int np = 0; np < 8; np++) {
                uint32_t vb4[4];
                LDSM4(vb4[0], vb4[1], vb4[2], vb4[3],
                      sb + 16384 + sw128((uint32_t)(np * 16 + lrow) * 128 + lcol + ks2 * 32));
                MMA_F16(oacc[2 * np],     pa, vb4[0], vb4[2]);
                MMA_F16(oacc[2 * np + 1], pa, vb4[1], vb4[3]);
            }
        }
        __syncthreads();
    }

    // ---- epilogue: normalize, write ctx fp16 ----
    l0 += __shfl_xor_sync(0xffffffffu, l0, 1);
    l0 += __shfl_xor_sync(0xffffffffu, l0, 2);
    l1 += __shfl_xor_sync(0xffffffffu, l1, 1);
    l1 += __shfl_xor_sync(0xffffffffu, l1, 2);
    const float inv0 = 1.f / l0, inv1 = 1.f / l1;
    const size_t row0 = (size_t)(b * SS + qb + wid * 16 + g);
#pragma unroll
    for (int nf = 0; nf < 16; nf++) {
        const int col = h * HDIM + nf * 8 + tg * 2;
        *(__half2*)(ch + row0 * DD + col) =
            __halves2half2(__float2half_rn(oacc[nf][0] * inv0),
                           __float2half_rn(oacc[nf][1] * inv0));
        *(__half2*)(ch + (row0 + 8) * DD + col) =
            __halves2half2(__float2half_rn(oacc[nf][2] * inv1),
                           __float2half_rn(oacc[nf][3] * inv1));
    }
}

// ---------------- launch ----------------
extern "C" void kernel_launch(void* const* d_in, const int* in_sizes, int n_in,
                              void* d_out, int out_size)
{
    const int*   ids      = (const int*)  d_in[0];
    const int*   pos      = (const int*)  d_in[1];
    const float* wte      = (const float*)d_in[2];
    const float* wpe      = (const float*)d_in[3];
    const float* c_attn_w = (const float*)d_in[4];
    const float* c_attn_b = (const float*)d_in[5];
    const float* c_proj_w = (const float*)d_in[6];
    const float* c_proj_b = (const float*)d_in[7];
    const float* ln1_w    = (const float*)d_in[8];
    const float* ln1_b    = (const float*)d_in[9];
    const float* ln2_w    = (const float*)d_in[10];
    const float* ln2_b    = (const float*)d_in[11];
    const float* fc_w     = (const float*)d_in[12];
    const float* fc_b     = (const float*)d_in[13];
    const float* mp_w     = (const float*)d_in[14];
    const float* mp_b     = (const float*)d_in[15];
    const float* lnf_w    = (const float*)d_in[16];
    const float* lnf_b    = (const float*)d_in[17];
    float* out = (float*)d_out;

    float *h, *res, *res2, *qkv, *attn;
    __half *xh, *ch, *fh, *wq, *wp, *wf, *wm;
    cudaGetSymbolAddress((void**)&h,    g_h);
    cudaGetSymbolAddress((void**)&res,  g_res);
    cudaGetSymbolAddress((void**)&res2, g_res2);
    cudaGetSymbolAddress((void**)&qkv,  g_qkv);
    cudaGetSymbolAddress((void**)&attn, g_attn);
    cudaGetSymbolAddress((void**)&xh,   g_xh);
    cudaGetSymbolAddress((void**)&ch,   g_ch);
    cudaGetSymbolAddress((void**)&fh,   g_fh);
    cudaGetSymbolAddress((void**)&wq,   g_wq);
    cudaGetSymbolAddress((void**)&wp,   g_wp);
    cudaGetSymbolAddress((void**)&wf,   g_wf);
    cudaGetSymbolAddress((void**)&wm,   g_wm);

    cudaFuncSetAttribute(gemm_kernel,  cudaFuncAttributeMaxDynamicSharedMemorySize, SMEM_GEMM);
    cudaFuncSetAttribute(fattn_kernel, cudaFuncAttributeMaxDynamicSharedMemorySize, SMEM_ATTN);

    const dim3 agrid(SS / 64, HH, BB);

    // Launch order: index 5 is fattn (ncu -s 5 -c 1 captures it).
    embed_kernel<<<(TT * DD + 255) / 256, 256>>>(ids, pos, wte, wpe, h);       // 0
    tsplit_kernel<<<dim3(QKN / 32, DD / 32), 256>>>(c_attn_w, wq, DD, QKN);    // 1
    tsplit_kernel<<<dim3(DD / 32, DD / 32), 256>>>(c_proj_w, wp, DD, DD);      // 2
    ln_kernel<<<TT, 256>>>(h, nullptr, ln1_w, ln1_b, res, nullptr, xh);        // 3
    gemm_kernel<<<dim3(QKN / 128, TT / 128), 256, SMEM_GEMM>>>(                // 4
        xh, wq, c_attn_b, qkv, nullptr, TT, QKN, DD, 0);
    fattn_kernel<<<agrid, 128, SMEM_ATTN>>>(qkv, ch);                          // 5 <- profiled
    tsplit_kernel<<<dim3(FFN / 32, DD / 32), 256>>>(fc_w, wf, DD, FFN);        // 6
    tsplit_kernel<<<dim3(DD / 32, FFN / 32), 256>>>(mp_w, wm, FFN, DD);        // 7
    gemm_kernel<<<dim3(DD / 128, TT / 128), 256, SMEM_GEMM>>>(
        ch, wp, c_proj_b, attn, nullptr, TT, DD, DD, 0);
    ln_kernel<<<TT, 256>>>(attn, res, ln2_w, ln2_b, res2, nullptr, xh);
    gemm_kernel<<<dim3(FFN / 128, TT / 128), 256, SMEM_GEMM>>>(
        xh, wf, fc_b, nullptr, fh, TT, FFN, DD, 1);
    gemm_kernel<<<dim3(DD / 128, TT / 128), 256, SMEM_GEMM>>>(
        fh, wm, mp_b, h, nullptr, TT, DD, FFN, 0);

    // remaining layers
    for (int l = 1; l < NL; l++) {
        tsplit_kernel<<<dim3(QKN / 32, DD / 32), 256>>>(
            c_attn_w + (size_t)l * DD * QKN, wq + (size_t)l * QKN * DD, DD, QKN);
        tsplit_kernel<<<dim3(DD / 32, DD / 32), 256>>>(
            c_proj_w + (size_t)l * DD * DD, wp + (size_t)l * DD * DD, DD, DD);
        tsplit_kernel<<<dim3(FFN / 32, DD / 32), 256>>>(
            fc_w + (size_t)l * DD * FFN, wf + (size_t)l * FFN * DD, DD, FFN);
        tsplit_kernel<<<dim3(DD / 32, FFN / 32), 256>>>(
            mp_w + (size_t)l * FFN * DD, wm + (size_t)l * DD * FFN, FFN, DD);

        ln_kernel<<<TT, 256>>>(h, res2, ln1_w + (size_t)l * DD, ln1_b + (size_t)l * DD,
                               res, nullptr, xh);
        gemm_kernel<<<dim3(QKN / 128, TT / 128), 256, SMEM_GEMM>>>(
            xh, wq + (size_t)l * QKN * DD,
            c_attn_b + (size_t)l * QKN, qkv, nullptr, TT, QKN, DD, 0);
        fattn_kernel<<<agrid, 128, SMEM_ATTN>>>(qkv, ch);
        gemm_kernel<<<dim3(DD / 128, TT / 128), 256, SMEM_GEMM>>>(
            ch, wp + (size_t)l * DD * DD,
            c_proj_b + (size_t)l * DD, attn, nullptr, TT, DD, DD, 0);
        ln_kernel<<<TT, 256>>>(attn, res, ln2_w + (size_t)l * DD, ln2_b + (size_t)l * DD,
                               res2, nullptr, xh);
        gemm_kernel<<<dim3(FFN / 128, TT / 128), 256, SMEM_GEMM>>>(
            xh, wf + (size_t)l * FFN * DD,
            fc_b + (size_t)l * FFN, nullptr, fh, TT, FFN, DD, 1);
        gemm_kernel<<<dim3(DD / 128, TT / 128), 256, SMEM_GEMM>>>(
            fh, wm + (size_t)l * DD * FFN,
            mp_b + (size_t)l * DD, h, nullptr, TT, DD, FFN, 0);
    }

    ln_kernel<<<TT, 256>>>(h, res2, lnf_w, lnf_b, nullptr, out, nullptr);
}

// round 11
// speedup vs baseline: 4.0937x; 1.0133x over previous
#include <cuda_runtime.h>
#include <cuda_fp16.h>
#include <math.h>
#include <stdint.h>

// ---------------- model constants ----------------
#define TT   2048
#define DD   2048
#define HH   16
#define HDIM 128
#define SS   1024
#define BB   2
#define FFN  8192
#define QKN  2304
#define NL   2
#define LN_EPS 1e-5f
#define ATT_SCALE 0.08838834764831845f

// ---------------- fp32 scratch ----------------
__device__ float g_h   [TT * DD];
__device__ float g_res [TT * DD];
__device__ float g_res2[TT * DD];
__device__ float g_attn[TT * DD];

// ---------------- fp16 activations ----------------
__device__ __align__(16) __half g_qkv[TT*QKN];
__device__ __align__(16) __half g_xh[TT*DD];
__device__ __align__(16) __half g_ch[TT*DD];
__device__ __align__(16) __half g_fh[TT*FFN];

// transposed weights [N][K], fp16
__device__ __align__(16) __half g_wq[NL*QKN*DD];
__device__ __align__(16) __half g_wp[NL*DD*DD];
__device__ __align__(16) __half g_wf[NL*FFN*DD];
__device__ __align__(16) __half g_wm[NL*DD*FFN];

// ---------------- PTX helpers (plain sm_80 features) ----------------
__device__ __forceinline__ uint32_t s2u(const void* p) {
    uint32_t a;
    asm("{ .reg .u64 t; cvta.to.shared.u64 t, %1; cvt.u32.u64 %0, t; }" : "=r"(a) : "l"(p));
    return a;
}
__device__ __forceinline__ uint32_t sw128(uint32_t o) { return o ^ ((o >> 3) & 0x70); }
__device__ __forceinline__ void cp16(uint32_t d, const void* s) {
    asm volatile("cp.async.cg.shared.global [%0], [%1], 16;" :: "r"(d), "l"(s));
}
#define CP_COMMIT() asm volatile("cp.async.commit_group;" ::: "memory")
#define CP_WAIT1()  asm volatile("cp.async.wait_group 1;" ::: "memory")
#define CP_WAIT0()  asm volatile("cp.async.wait_group 0;" ::: "memory")

#define LDSM4(R0, R1, R2, R3, ADDR) \
    asm volatile("ldmatrix.sync.aligned.m8n8.x4.shared.b16 {%0,%1,%2,%3}, [%4];" \
        : "=r"(R0), "=r"(R1), "=r"(R2), "=r"(R3) : "r"(ADDR))

#define MMA_F16(D, A, B0, B1) \
    asm volatile("mma.sync.aligned.m16n8k16.row.col.f32.f16.f16.f32 " \
        "{%0,%1,%2,%3}, {%4,%5,%6,%7}, {%8,%9}, {%0,%1,%2,%3};" \
        : "+f"((D)[0]), "+f"((D)[1]), "+f"((D)[2]), "+f"((D)[3]) \
        : "r"((A)[0]), "r"((A)[1]), "r"((A)[2]), "r"((A)[3]), "r"(B0), "r"(B1))

__device__ __forceinline__ uint32_t packh2(float a, float b) {
    __half2 t = __halves2half2(__float2half_rn(a), __float2half_rn(b));
    return *(uint32_t*)&t;
}

// ---------------- embed ----------------
__global__ void embed_kernel(const int* __restrict__ ids, const int* __restrict__ pos,
                             const float* __restrict__ wte, const float* __restrict__ wpe,
                             float* __restrict__ out)
{
    int idx = blockIdx.x * blockDim.x + threadIdx.x;
    if (idx >= TT * DD) return;
    int t = idx >> 11, d = idx & (DD - 1);
    out[idx] = wte[(size_t)ids[t] * DD + d] + wpe[(size_t)pos[t] * DD + d];
}

// ---------------- fused residual-add + LayerNorm (+ fp16 out) ----------------
__global__ __launch_bounds__(256)
void ln_kernel(const float* __restrict__ a, const float* __restrict__ r,
               const float* __restrict__ g, const float* __restrict__ b,
               float* __restrict__ res_out, float* __restrict__ xf,
               __half* __restrict__ xh)
{
    const int t = blockIdx.x;
    const size_t base = (size_t)t * DD;
    float v[8];
    float s = 0.f, sq = 0.f;
#pragma unroll
    for (int i = 0; i < 8; i++) {
        int idx = threadIdx.x + i * 256;
        float val = a[base + idx];
        if (r) val += r[base + idx];
        v[i] = val; s += val; sq += val * val;
    }
    int lane = threadIdx.x & 31, wid = threadIdx.x >> 5;
#pragma unroll
    for (int o = 16; o; o >>= 1) {
        s  += __shfl_xor_sync(0xffffffffu, s,  o);
        sq += __shfl_xor_sync(0xffffffffu, sq, o);
    }
    __shared__ float shs[8], shq[8], smean, srstd;
    if (lane == 0) { shs[wid] = s; shq[wid] = sq; }
    __syncthreads();
    if (wid == 0) {
        float ts = (lane < 8) ? shs[lane] : 0.f;
        float tq = (lane < 8) ? shq[lane] : 0.f;
#pragma unroll
        for (int o = 4; o; o >>= 1) {
            ts += __shfl_xor_sync(0xffffffffu, ts, o);
            tq += __shfl_xor_sync(0xffffffffu, tq, o);
        }
        if (lane == 0) {
            float mean = ts * (1.f / DD);
            float var  = tq * (1.f / DD) - mean * mean;
            smean = mean; srstd = rsqrtf(var + LN_EPS);
        }
    }
    __syncthreads();
    float mean = smean, rstd = srstd;
#pragma unroll
    for (int i = 0; i < 8; i++) {
        int idx = threadIdx.x + i * 256;
        if (res_out) res_out[base + idx] = v[i];
        float y = (v[i] - mean) * rstd * g[idx] + b[idx];
        if (xf) xf[base + idx] = y;
        if (xh) xh[base + idx] = __float2half_rn(y);
    }
}

// ---------------- weight transpose: W[K][N] -> fp16[N][K] (vectorized stores) ----------------
// tile: 64 K x 32 N. grid = (N/32, K/64).
__global__ __launch_bounds__(256)
void tsplit_kernel(const float* __restrict__ W, __half* __restrict__ Th, int K, int N)
{
    __shared__ float t[64][33];
    const int k0 = blockIdx.y * 64, n0 = blockIdx.x * 32;
    const int tn = threadIdx.x & 31, tk = threadIdx.x >> 5;
#pragma unroll
    for (int i = 0; i < 8; i++) {
        int k = tk + i * 8;
        t[k][tn] = W[(size_t)(k0 + k) * N + n0 + tn];
    }
    __syncthreads();
#pragma unroll
    for (int i = 0; i < 4; i++) {
        int n = tk + i * 8;
        float a = t[tn * 2][n], b = t[tn * 2 + 1][n];
        *(__half2*)(Th + (size_t)(n0 + n) * K + k0 + tn * 2) =
            __halves2half2(__float2half_rn(a), __float2half_rn(b));
    }
}

// ---------------- pure fp16 warp-MMA GEMM (single pass) ----------------
#define SMEM_GEMM 65536
#define BUFSZ 32768

__device__ __forceinline__ void load_tiles(
    const __half* Ah, const __half* Bh,
    uint32_t base, int bm, int bn, int k0, int K, int tid)
{
#pragma unroll
    for (int i = 0; i < 4; i++) {
        int idx = tid + i * 256;
        int row = idx >> 3, seg = idx & 7;
        cp16(base + sw128(row * 128 + seg * 16),
             Ah + (size_t)(bm + row) * K + k0 + seg * 8);
    }
#pragma unroll
    for (int i = 0; i < 4; i++) {
        int idx = tid + i * 256;
        int row = idx >> 3, seg = idx & 7;
        cp16(base + 16384 + sw128(row * 128 + seg * 16),
             Bh + (size_t)(bn + row) * K + k0 + seg * 8);
    }
}

__device__ __forceinline__ float gelu_tanh(float x) {
    float x3 = x * x * x;
    float t = tanhf(0.7978845608028654f * (x + 0.044715f * x3));
    return 0.5f * x * (1.f + t);
}

__global__ __launch_bounds__(256, 2)
void gemm_kernel(const __half* __restrict__ Ah, const __half* __restrict__ Bh,
                 const float* __restrict__ bias, float* __restrict__ Cf,
                 __half* __restrict__ Ch,
                 int M, int N, int K, int act)
{
    extern __shared__ char smem[];
    const uint32_t sb = s2u(smem);
    const int tid = threadIdx.x;
    const int bm = blockIdx.y * 128, bn = blockIdx.x * 128;
    const int lane = tid & 31, wid = tid >> 5;
    const int wm = wid >> 2, wn = wid & 3;

    const int lrow = lane & 15;
    const uint32_t lcol = (uint32_t)(lane >> 4) * 16;
    uint32_t aOff[4], bOff[2];
#pragma unroll
    for (int mf = 0; mf < 4; mf++)
        aOff[mf] = (uint32_t)(wm * 64 + mf * 16 + lrow) * 128 + lcol;
#pragma unroll
    for (int np = 0; np < 2; np++)
        bOff[np] = (uint32_t)(wn * 32 + np * 16 + lrow) * 128 + lcol;

    float acc[4][4][4];
#pragma unroll
    for (int i = 0; i < 4; i++)
#pragma unroll
        for (int j = 0; j < 4; j++)
#pragma unroll
            for (int c = 0; c < 4; c++) acc[i][j][c] = 0.f;

    const int nk = K >> 6;
    load_tiles(Ah, Bh, sb,         bm, bn, 0,  K, tid); CP_COMMIT();
    load_tiles(Ah, Bh, sb + BUFSZ, bm, bn, 64, K, tid); CP_COMMIT();

    for (int it = 0; it < nk; it++) {
        const int b = it & 1;
        if (it + 2 <= nk) { CP_WAIT1(); } else { CP_WAIT0(); }
        __syncthreads();

        const uint32_t ahS = sb + (uint32_t)b * BUFSZ;
        const uint32_t bhS = ahS + 16384;

#pragma unroll
        for (int ks = 0; ks < 4; ks++) {
            const uint32_t ko = (uint32_t)ks * 32;
            uint32_t af[4][4], bh[2][4];
#pragma unroll
            for (int np = 0; np < 2; np++)
                LDSM4(bh[np][0], bh[np][1], bh[np][2], bh[np][3], bhS + sw128(bOff[np] + ko));
#pragma unroll
            for (int mf = 0; mf < 4; mf++)
                LDSM4(af[mf][0], af[mf][1], af[mf][2], af[mf][3], ahS + sw128(aOff[mf] + ko));
#pragma unroll
            for (int mf = 0; mf < 4; mf++)
#pragma unroll
                for (int nf = 0; nf < 4; nf++)
                    MMA_F16(acc[mf][nf], af[mf], bh[nf >> 1][nf & 1], bh[nf >> 1][(nf & 1) + 2]);
        }

        __syncthreads();
        if (it + 2 < nk) {
            load_tiles(Ah, Bh, sb + (uint32_t)b * BUFSZ, bm, bn, (it + 2) * 64, K, tid);
            CP_COMMIT();
        }
    }

    const int g = lane >> 2, tg = lane & 3;
#pragma unroll
    for (int mf = 0; mf < 4; mf++) {
#pragma unroll
        for (int nf = 0; nf < 4; nf++) {
            const int col = bn + wn * 32 + nf * 8 + tg * 2;
            const float bxv = bias[col], byv = bias[col + 1];
#pragma unroll
            for (int half = 0; half < 2; half++) {
                const int row = bm + wm * 64 + mf * 16 + g + half * 8;
                float vx = acc[mf][nf][half * 2 + 0] + bxv;
                float vy = acc[mf][nf][half * 2 + 1] + byv;
                if (act) { vx = gelu_tanh(vx); vy = gelu_tanh(vy); }
                const size_t o = (size_t)row * N + col;
                if (Cf) { float2 f2 = make_float2(vx, vy); *(float2*)(Cf + o) = f2; }
                if (Ch) *(__half2*)(Ch + o) =
                    __halves2half2(__float2half_rn(vx), __float2half_rn(vy));
            }
        }
    }
}

// ---------------- tensor-core flash attention (MQA, causal, fp16 qkv input) ----------------
// Block = (qtile 64, head, batch), 128 threads (4 warps x 16 q-rows).
// SMEM 32KB: Q panels (16KB) then reuse as Kh(16KB) | Vth(16KB).
#define SMEM_ATTN 32768

__global__ __launch_bounds__(128)
void fattn_kernel(const __half* __restrict__ qkv, __half* __restrict__ ch)
{
    extern __shared__ char smem[];
    char* smc = smem;
    const uint32_t sb = s2u(smem);
    const int tid = threadIdx.x, lane = tid & 31, wid = tid >> 5;
    const int qb = blockIdx.x * 64;
    const int h  = blockIdx.y;
    const int b  = blockIdx.z;
    const int lrow = lane & 15;
    const uint32_t lcol = (uint32_t)(lane >> 4) * 16;
    const int g = lane >> 2, tg = lane & 3;

    // ---- stage Q (scaled fp16) into two 8KB panels ----
    {
        const __half* qsrc = qkv + (size_t)(b * SS + qb) * QKN + h * HDIM;
#pragma unroll
        for (int i = 0; i < 16; i++) {
            int idx = tid + i * 128;
            int r = idx >> 5, ds = idx & 31;
            uint2 raw = *(const uint2*)(qsrc + (size_t)r * QKN + ds * 4);
            float2 f0 = __half22float2(*(__half2*)&raw.x);
            float2 f1 = __half22float2(*(__half2*)&raw.y);
            uint32_t off = (uint32_t)(ds >> 4) * 8192 +
                           sw128((uint32_t)r * 128 + (ds & 15) * 8);
            uint2 wh;
            wh.x = packh2(f0.x * ATT_SCALE, f0.y * ATT_SCALE);
            wh.y = packh2(f1.x * ATT_SCALE, f1.y * ATT_SCALE);
            *(uint2*)(smc + off) = wh;
        }
    }
    __syncthreads();

    // ---- Q fragments (registers, all chunks) ----
    uint32_t qf[8][4];
    {
        uint32_t qOff = (uint32_t)(wid * 16 + lrow) * 128 + lcol;
#pragma unroll
        for (int ks = 0; ks < 8; ks++) {
            uint32_t a = sb + (uint32_t)(ks >> 2) * 8192 + sw128(qOff + (ks & 3) * 32);
            LDSM4(qf[ks][0], qf[ks][1], qf[ks][2], qf[ks][3], a);
        }
    }
    __syncthreads();

    float oacc[16][4];
#pragma unroll
    for (int i = 0; i < 16; i++)
#pragma unroll
        for (int c = 0; c < 4; c++) oacc[i][c] = 0.f;
    float m0 = -1e30f, m1 = -1e30f, l0 = 0.f, l1 = 0.f;

    const int nchunks = qb / 64 + 1;
    const __half* kvb = qkv + (size_t)(b * SS) * QKN + DD;

    for (int kc = 0; kc < nchunks; kc++) {
        // ---- K chunk -> panels at 0 / 8192 (raw fp16 copy, no convert) ----
#pragma unroll
        for (int i = 0; i < 16; i++) {
            int idx = tid + i * 128;
            int key = idx >> 5, ds = idx & 31;
            uint2 raw = *(const uint2*)(kvb + (size_t)(kc * 64 + key) * QKN + ds * 4);
            uint32_t off = (uint32_t)(ds >> 4) * 8192 +
                           sw128((uint32_t)key * 128 + (ds & 15) * 8);
            *(uint2*)(smc + off) = raw;
        }
        // ---- V chunk -> Vth transposed [dim][key] at 16384 (fp16 scatter) ----
#pragma unroll
        for (int i = 0; i < 16; i++) {
            int idx = tid + i * 128;
            int key = idx & 63, ds = idx >> 6;
            uint2 raw = *(const uint2*)(kvb + (size_t)(kc * 64 + key) * QKN + HDIM + ds * 4);
            const __half* vp = (const __half*)&raw;
#pragma unroll
            for (int j = 0; j < 4; j++) {
                int d = ds * 4 + j;
                *(__half*)(smc + 16384 + sw128((uint32_t)d * 128 + key * 2)) = vp[j];
            }
        }
        __syncthreads();

        // ---- S = Q @ K^T ----
        float sacc[8][4];
#pragma unroll
        for (int i = 0; i < 8; i++)
#pragma unroll
            for (int c = 0; c < 4; c++) sacc[i][c] = 0.f;
#pragma unroll
        for (int ks = 0; ks < 8; ks++) {
            uint32_t kb4[4][4];
#pragma unroll
            for (int np = 0; np < 4; np++)
                LDSM4(kb4[np][0], kb4[np][1], kb4[np][2], kb4[np][3],
                      sb + (uint32_t)(ks >> 2) * 8192 +
                      sw128((uint32_t)(np * 16 + lrow) * 128 + lcol + (ks & 3) * 32));
#pragma unroll
            for (int nf = 0; nf < 8; nf++)
                MMA_F16(sacc[nf], qf[ks],
                        kb4[nf >> 1][nf & 1], kb4[nf >> 1][(nf & 1) + 2]);
        }

        // ---- causal mask on diagonal chunk ----
        if (kc * 64 == qb) {
            const int r0 = wid * 16 + g, r1 = r0 + 8;
#pragma unroll
            for (int nf = 0; nf < 8; nf++) {
                int c0 = nf * 8 + tg * 2;
                if (c0 > r0)     sacc[nf][0] = -1e30f;
                if (c0 + 1 > r0) sacc[nf][1] = -1e30f;
                if (c0 > r1)     sacc[nf][2] = -1e30f;
                if (c0 + 1 > r1) sacc[nf][3] = -1e30f;
            }
        }

        // ---- online softmax ----
        float mx0 = m0, mx1 = m1;
#pragma unroll
        for (int nf = 0; nf < 8; nf++) {
            mx0 = fmaxf(mx0, fmaxf(sacc[nf][0], sacc[nf][1]));
            mx1 = fmaxf(mx1, fmaxf(sacc[nf][2], sacc[nf][3]));
        }
        mx0 = fmaxf(mx0, __shfl_xor_sync(0xffffffffu, mx0, 1));
        mx0 = fmaxf(mx0, __shfl_xor_sync(0xffffffffu, mx0, 2));
        mx1 = fmaxf(mx1, __shfl_xor_sync(0xffffffffu, mx1, 1));
        mx1 = fmaxf(mx1, __shfl_xor_sync(0xffffffffu, mx1, 2));
        float sc0 = __expf(m0 - mx0), sc1 = __expf(m1 - mx1);
        m0 = mx0; m1 = mx1;
        l0 *= sc0; l1 *= sc1;
#pragma unroll
        for (int nf = 0; nf < 16; nf++) {
            oacc[nf][0] *= sc0; oacc[nf][1] *= sc0;
            oacc[nf][2] *= sc1; oacc[nf][3] *= sc1;
        }
        uint32_t pp[8][2];
#pragma unroll
        for (int nf = 0; nf < 8; nf++) {
            float e0 = __expf(sacc[nf][0] - mx0), e1 = __expf(sacc[nf][1] - mx0);
            float e2 = __expf(sacc[nf][2] - mx1), e3 = __expf(sacc[nf][3] - mx1);
            l0 += e0 + e1; l1 += e2 + e3;
            pp[nf][0] = packh2(e0, e1);
            pp[nf][1] = packh2(e2, e3);
        }

        // ---- O += P @ V ----
#pragma unroll
        for (int ks2 = 0; ks2 < 4; ks2++) {
            uint32_t pa[4] = { pp[2 * ks2][0], pp[2 * ks2][1],
                               pp[2 * ks2 + 1][0], pp[2 * ks2 + 1][1] };
#pragma unroll
            for (int np = 0; np < 8; np++) {
                uint32_t vb4[4];
                LDSM4(vb4[0], vb4[1], vb4[2], vb4[3],
                      sb + 16384 + sw128((uint32_t)(np * 16 + lrow) * 128 + lcol + ks2 * 32));
                MMA_F16(oacc[2 * np],     pa, vb4[0], vb4[2]);
                MMA_F16(oacc[2 * np + 1], pa, vb4[1], vb4[3]);
            }
        }
        __syncthreads();
    }

    // ---- epilogue: normalize, write ctx fp16 ----
    l0 += __shfl_xor_sync(0xffffffffu, l0, 1);
    l0 += __shfl_xor_sync(0xffffffffu, l0, 2);
    l1 += __shfl_xor_sync(0xffffffffu, l1, 1);
    l1 += __shfl_xor_sync(0xffffffffu, l1, 2);
    const float inv0 = 1.f / l0, inv1 = 1.f / l1;
    const size_t row0 = (size_t)(b * SS + qb + wid * 16 + g);
#pragma unroll
    for (int nf = 0; nf < 16; nf++) {
        const int col = h * HDIM + nf * 8 + tg * 2;
        *(__half2*)(ch + row0 * DD + col) =
            __halves2half2(__float2half_rn(oacc[nf][0] * inv0),
                           __float2half_rn(oacc[nf][1] * inv0));
        *(__half2*)(ch + (row0 + 8) * DD + col) =
            __halves2half2(__float2half_rn(oacc[nf][2] * inv1),
                           __float2half_rn(oacc[nf][3] * inv1));
    }
}

// ---------------- launch ----------------
extern "C" void kernel_launch(void* const* d_in, const int* in_sizes, int n_in,
                              void* d_out, int out_size)
{
    const int*   ids      = (const int*)  d_in[0];
    const int*   pos      = (const int*)  d_in[1];
    const float* wte      = (const float*)d_in[2];
    const float* wpe      = (const float*)d_in[3];
    const float* c_attn_w = (const float*)d_in[4];
    const float* c_attn_b = (const float*)d_in[5];
    const float* c_proj_w = (const float*)d_in[6];
    const float* c_proj_b = (const float*)d_in[7];
    const float* ln1_w    = (const float*)d_in[8];
    const float* ln1_b    = (const float*)d_in[9];
    const float* ln2_w    = (const float*)d_in[10];
    const float* ln2_b    = (const float*)d_in[11];
    const float* fc_w     = (const float*)d_in[12];
    const float* fc_b     = (const float*)d_in[13];
    const float* mp_w     = (const float*)d_in[14];
    const float* mp_b     = (const float*)d_in[15];
    const float* lnf_w    = (const float*)d_in[16];
    const float* lnf_b    = (const float*)d_in[17];
    float* out = (float*)d_out;

    float *h, *res, *res2, *attn;
    __half *qkv, *xh, *ch, *fh, *wq, *wp, *wf, *wm;
    cudaGetSymbolAddress((void**)&h,    g_h);
    cudaGetSymbolAddress((void**)&res,  g_res);
    cudaGetSymbolAddress((void**)&res2, g_res2);
    cudaGetSymbolAddress((void**)&attn, g_attn);
    cudaGetSymbolAddress((void**)&qkv,  g_qkv);
    cudaGetSymbolAddress((void**)&xh,   g_xh);
    cudaGetSymbolAddress((void**)&ch,   g_ch);
    cudaGetSymbolAddress((void**)&fh,   g_fh);
    cudaGetSymbolAddress((void**)&wq,   g_wq);
    cudaGetSymbolAddress((void**)&wp,   g_wp);
    cudaGetSymbolAddress((void**)&wf,   g_wf);
    cudaGetSymbolAddress((void**)&wm,   g_wm);

    cudaFuncSetAttribute(gemm_kernel,  cudaFuncAttributeMaxDynamicSharedMemorySize, SMEM_GEMM);
    cudaFuncSetAttribute(fattn_kernel, cudaFuncAttributeMaxDynamicSharedMemorySize, SMEM_ATTN);

    const dim3 agrid(SS / 64, HH, BB);

    // Launch order: index 5 is fattn (ncu -s 5 -c 1 captures it).
    embed_kernel<<<(TT * DD + 255) / 256, 256>>>(ids, pos, wte, wpe, h);       // 0
    tsplit_kernel<<<dim3(QKN / 32, DD / 64), 256>>>(c_attn_w, wq, DD, QKN);    // 1
    tsplit_kernel<<<dim3(DD / 32, DD / 64), 256>>>(c_proj_w, wp, DD, DD);      // 2
    ln_kernel<<<TT, 256>>>(h, nullptr, ln1_w, ln1_b, res, nullptr, xh);        // 3
    gemm_kernel<<<dim3(QKN / 128, TT / 128), 256, SMEM_GEMM>>>(                // 4
        xh, wq, c_attn_b, nullptr, qkv, TT, QKN, DD, 0);
    fattn_kernel<<<agrid, 128, SMEM_ATTN>>>(qkv, ch);                          // 5 <- profiled
    tsplit_kernel<<<dim3(FFN / 32, DD / 64), 256>>>(fc_w, wf, DD, FFN);        // 6
    tsplit_kernel<<<dim3(DD / 32, FFN / 64), 256>>>(mp_w, wm, FFN, DD);        // 7
    gemm_kernel<<<dim3(DD / 128, TT / 128), 256, SMEM_GEMM>>>(
        ch, wp, c_proj_b, attn, nullptr, TT, DD, DD, 0);
    ln_kernel<<<TT, 256>>>(attn, res, ln2_w, ln2_b, res2, nullptr, xh);
    gemm_kernel<<<dim3(FFN / 128, TT / 128), 256, SMEM_GEMM>>>(
        xh, wf, fc_b, nullptr, fh, TT, FFN, DD, 1);
    gemm_kernel<<<dim3(DD / 128, TT / 128), 256, SMEM_GEMM>>>(
        fh, wm, mp_b, h, nullptr, TT, DD, FFN, 0);

    // remaining layers
    for (int l = 1; l < NL; l++) {
        tsplit_kernel<<<dim3(QKN / 32, DD / 64), 256>>>(
            c_attn_w + (size_t)l * DD * QKN, wq + (size_t)l * QKN * DD, DD, QKN);
        tsplit_kernel<<<dim3(DD / 32, DD / 64), 256>>>(
            c_proj_w + (size_t)l * DD * DD, wp + (size_t)l * DD * DD, DD, DD);
        tsplit_kernel<<<dim3(FFN / 32, DD / 64), 256>>>(
            fc_w + (size_t)l * DD * FFN, wf + (size_t)l * FFN * DD, DD, FFN);
        tsplit_kernel<<<dim3(DD / 32, FFN / 64), 256>>>(
            mp_w + (size_t)l * FFN * DD, wm + (size_t)l * DD * FFN, FFN, DD);

        ln_kernel<<<TT, 256>>>(h, res2, ln1_w + (size_t)l * DD, ln1_b + (size_t)l * DD,
                               res, nullptr, xh);
        gemm_kernel<<<dim3(QKN / 128, TT / 128), 256, SMEM_GEMM>>>(
            xh, wq + (size_t)l * QKN * DD,
            c_attn_b + (size_t)l * QKN, nullptr, qkv, TT, QKN, DD, 0);
        fattn_kernel<<<agrid, 128, SMEM_ATTN>>>(qkv, ch);
        gemm_kernel<<<dim3(DD / 128, TT / 128), 256, SMEM_GEMM>>>(
            ch, wp + (size_t)l * DD * DD,
            c_proj_b + (size_t)l * DD, attn, nullptr, TT, DD, DD, 0);
        ln_kernel<<<TT, 256>>>(attn, res, ln2_w + (size_t)l * DD, ln2_b + (size_t)l * DD,
                               res2, nullptr, xh);
        gemm_kernel<<<dim3(FFN / 128, TT / 128), 256, SMEM_GEMM>>>(
            xh, wf + (size_t)l * FFN * DD,
            fc_b + (size_t)l * FFN, nullptr, fh, TT, FFN, DD, 1);
        gemm_kernel<<<dim3(DD / 128, TT / 128), 256, SMEM_GEMM>>>(
            fh, wm + (size_t)l * DD * FFN,
            mp_b + (size_t)l * DD, h, nullptr, TT, DD, FFN, 0);
    }

    ln_kernel<<<TT, 256>>>(h, res2, lnf_w, lnf_b, nullptr, out, nullptr);
}